// round 2
// baseline (speedup 1.0000x reference)
#include <cuda_runtime.h>
#include <math.h>

#define NTOK 98
#define CDIM 256
#define NHEAD 8
#define DH 32
#define XPAD 260   // x_s row stride (floats): 16B-aligned rows, conflict-free broadcasts
#define KPAD 33    // q/k/v row stride
#define SPAD 99    // S row stride
#define MAXB 2048

// scratch: per-head attention output in [B, N, C] layout (205.5 MB)
__device__ float g_attn_out[(size_t)MAXB * NTOK * CDIM];

extern __shared__ float smem[];

// ===========================================================================
// Kernel 1: per-window fused qkv + attention (all 8 heads) -> g_attn_out
// smem: x_s[98*260] | q_s[98*33] | k_s | v_s | S[98*99] | base[98] (int)
// ===========================================================================
__global__ void __launch_bounds__(256, 1)
attn_kernel(const float* __restrict__ x,
            const float* __restrict__ mask,
            const float* __restrict__ qkv_w,
            const float* __restrict__ bias_table,
            int nW)
{
    float* x_s = smem;
    float* q_s = x_s + NTOK * XPAD;
    float* k_s = q_s + NTOK * KPAD;
    float* v_s = k_s + NTOK * KPAD;
    float* S   = v_s + NTOK * KPAD;
    int*   base = (int*)(S + NTOK * SPAD);

    const int b   = blockIdx.x;
    const int tid = threadIdx.x;
    const int wi  = b % nW;

    // stage x[b] into padded smem
    {
        const float4* xg = (const float4*)(x + (size_t)b * NTOK * CDIM);
        for (int i = tid; i < NTOK * CDIM / 4; i += 256) {
            int row = i >> 6;            // / (256/4)
            int c4  = (i & 63) << 2;
            *(float4*)&x_s[row * XPAD + c4] = xg[i];
        }
    }
    // relative-position base code per token: idx(n,m) = base[n]-base[m]+253
    if (tid < NTOK) {
        int d = tid / 49, rem = tid % 49;
        base[tid] = d * 169 + (rem / 7) * 13 + (rem % 7);
    }
    __syncthreads();

    const int rg   = tid >> 4;   // row group 0..15 (14 used: 14*7 = 98 rows)
    const int cg   = tid & 15;   // col lane 0..15
    const bool act = (rg < 14);
    const int n0   = rg * 7;
    const int lane = tid & 31;
    const int warp = tid >> 5;

    for (int h = 0; h < NHEAD; ++h) {
        // ---- Phase B: q,k,v = x @ W_h  (outputs [98, 96]) -----------------
        if (act) {
            int col[6];
            #pragma unroll
            for (int u = 0; u < 6; ++u) {
                int jj  = cg + 16 * u;          // 0..95
                int grp = jj >> 5;              // 0:q 1:k 2:v
                col[u] = grp * CDIM + h * DH + (jj & 31);
            }
            float acc[7][6];
            #pragma unroll
            for (int r = 0; r < 7; ++r)
                #pragma unroll
                for (int u = 0; u < 6; ++u) acc[r][u] = 0.f;

            #pragma unroll 4
            for (int c = 0; c < CDIM; ++c) {
                float wv[6];
                #pragma unroll
                for (int u = 0; u < 6; ++u)
                    wv[u] = __ldg(&qkv_w[(size_t)c * (3 * CDIM) + col[u]]);
                #pragma unroll
                for (int r = 0; r < 7; ++r) {
                    float xv = x_s[(n0 + r) * XPAD + c];
                    #pragma unroll
                    for (int u = 0; u < 6; ++u)
                        acc[r][u] = fmaf(xv, wv[u], acc[r][u]);
                }
            }
            #pragma unroll
            for (int u = 0; u < 6; ++u) {
                int jj  = cg + 16 * u;
                int grp = jj >> 5;
                int wn  = jj & 31;
                float* dst = (grp == 0) ? q_s : (grp == 1) ? k_s : v_s;
                #pragma unroll
                for (int r = 0; r < 7; ++r)
                    dst[(n0 + r) * KPAD + wn] = acc[r][u];
            }
        }
        __syncthreads();

        // ---- Phase C: S = scale * q k^T + bias + mask ---------------------
        if (act) {
            float acc[7][7];
            #pragma unroll
            for (int r = 0; r < 7; ++r)
                #pragma unroll
                for (int v = 0; v < 7; ++v) acc[r][v] = 0.f;

            int mm[7];
            #pragma unroll
            for (int v = 0; v < 7; ++v) {
                int m = cg + 16 * v;
                mm[v] = (m < NTOK) ? m : (NTOK - 1);   // clamp; result unused
            }
            #pragma unroll 8
            for (int c = 0; c < DH; ++c) {
                float kv[7], qv[7];
                #pragma unroll
                for (int v = 0; v < 7; ++v) kv[v] = k_s[mm[v] * KPAD + c];
                #pragma unroll
                for (int r = 0; r < 7; ++r) qv[r] = q_s[(n0 + r) * KPAD + c];
                #pragma unroll
                for (int r = 0; r < 7; ++r)
                    #pragma unroll
                    for (int v = 0; v < 7; ++v)
                        acc[r][v] = fmaf(qv[r], kv[v], acc[r][v]);
            }
            const float scale = 0.17677669529663689f;  // 32^-0.5
            #pragma unroll
            for (int v = 0; v < 7; ++v) {
                int m = cg + 16 * v;
                if (m < NTOK) {
                    #pragma unroll
                    for (int r = 0; r < 7; ++r) {
                        int n   = n0 + r;
                        int idx = base[n] - base[m] + 253;
                        float bi = __ldg(&bias_table[idx * NHEAD + h]);
                        float mk = __ldg(&mask[((size_t)wi * NTOK + n) * NTOK + m]);
                        S[n * SPAD + m] = acc[r][v] * scale + bi + mk;
                    }
                }
            }
        }
        __syncthreads();

        // ---- softmax over rows (warp per row) -----------------------------
        for (int n = warp; n < NTOK; n += 8) {
            float vals[4];
            float mx = -INFINITY;
            #pragma unroll
            for (int k2 = 0; k2 < 4; ++k2) {
                int m = lane + 32 * k2;
                vals[k2] = (m < NTOK) ? S[n * SPAD + m] : -INFINITY;
                mx = fmaxf(mx, vals[k2]);
            }
            #pragma unroll
            for (int o = 16; o > 0; o >>= 1)
                mx = fmaxf(mx, __shfl_xor_sync(0xffffffffu, mx, o));
            float sum = 0.f;
            #pragma unroll
            for (int k2 = 0; k2 < 4; ++k2) {
                int m = lane + 32 * k2;
                if (m < NTOK) { vals[k2] = __expf(vals[k2] - mx); sum += vals[k2]; }
            }
            #pragma unroll
            for (int o = 16; o > 0; o >>= 1)
                sum += __shfl_xor_sync(0xffffffffu, sum, o);
            float inv = __fdividef(1.f, sum);
            #pragma unroll
            for (int k2 = 0; k2 < 4; ++k2) {
                int m = lane + 32 * k2;
                if (m < NTOK) S[n * SPAD + m] = vals[k2] * inv;
            }
        }
        __syncthreads();

        // ---- Phase D: O = P @ V -> g_attn_out[b, n, h*32 + j] -------------
        if (act) {
            float a0[7], a1[7];
            #pragma unroll
            for (int r = 0; r < 7; ++r) { a0[r] = 0.f; a1[r] = 0.f; }
            #pragma unroll 2
            for (int m = 0; m < NTOK; ++m) {
                float v0 = v_s[m * KPAD + cg];
                float v1 = v_s[m * KPAD + cg + 16];
                #pragma unroll
                for (int r = 0; r < 7; ++r) {
                    float p = S[(n0 + r) * SPAD + m];
                    a0[r] = fmaf(p, v0, a0[r]);
                    a1[r] = fmaf(p, v1, a1[r]);
                }
            }
            #pragma unroll
            for (int r = 0; r < 7; ++r) {
                int n = n0 + r;
                float* o = g_attn_out + ((size_t)b * NTOK + n) * CDIM + h * DH;
                o[cg]      = a0[r];
                o[cg + 16] = a1[r];
            }
        }
        __syncthreads();   // q/k/v/S reused next head
    }
}

// ===========================================================================
// Kernel 2: out = attn_out @ proj_w + proj_b     (per-window block)
// ===========================================================================
__global__ void __launch_bounds__(256, 1)
proj_kernel(const float* __restrict__ proj_w,
            const float* __restrict__ proj_b,
            float* __restrict__ out)
{
    float* a_s = smem;
    const int b   = blockIdx.x;
    const int tid = threadIdx.x;

    const float4* ag = (const float4*)(g_attn_out + (size_t)b * NTOK * CDIM);
    for (int i = tid; i < NTOK * CDIM / 4; i += 256) {
        int row = i >> 6;
        int c4  = (i & 63) << 2;
        *(float4*)&a_s[row * XPAD + c4] = ag[i];
    }
    __syncthreads();

    const int rg = tid >> 4;
    const int cg = tid & 15;
    if (rg >= 14) return;                  // no further syncs below
    const int n0 = rg * 7;

    float acc[7][16];
    #pragma unroll
    for (int r = 0; r < 7; ++r)
        #pragma unroll
        for (int u = 0; u < 16; ++u) acc[r][u] = 0.f;

    #pragma unroll 2
    for (int c = 0; c < CDIM; ++c) {
        float wv[16];
        #pragma unroll
        for (int u = 0; u < 16; ++u)
            wv[u] = __ldg(&proj_w[(size_t)c * CDIM + cg + 16 * u]);
        #pragma unroll
        for (int r = 0; r < 7; ++r) {
            float xv = a_s[(n0 + r) * XPAD + c];
            #pragma unroll
            for (int u = 0; u < 16; ++u)
                acc[r][u] = fmaf(xv, wv[u], acc[r][u]);
        }
    }

    float bv[16];
    #pragma unroll
    for (int u = 0; u < 16; ++u) bv[u] = __ldg(&proj_b[cg + 16 * u]);

    #pragma unroll
    for (int r = 0; r < 7; ++r) {
        int n = n0 + r;
        float* o = out + ((size_t)b * NTOK + n) * CDIM;
        #pragma unroll
        for (int u = 0; u < 16; ++u)
            o[cg + 16 * u] = acc[r][u] + bv[u];
    }
}

// ===========================================================================
extern "C" void kernel_launch(void* const* d_in, const int* in_sizes, int n_in,
                              void* d_out, int out_size)
{
    const float* x          = (const float*)d_in[0];
    const float* mask       = (const float*)d_in[1];
    const float* qkv_w      = (const float*)d_in[2];
    const float* proj_w     = (const float*)d_in[3];
    const float* proj_b     = (const float*)d_in[4];
    const float* bias_table = (const float*)d_in[5];

    int B  = in_sizes[0] / (NTOK * CDIM);   // 2048
    int nW = in_sizes[1] / (NTOK * NTOK);   // 64
    if (B > MAXB) B = MAXB;

    const size_t smem1 = (size_t)(NTOK * XPAD + 3 * NTOK * KPAD + NTOK * SPAD) * 4
                         + NTOK * 4;                 // 179,928 B
    const size_t smem2 = (size_t)(NTOK * XPAD) * 4;  // 101,920 B

    cudaFuncSetAttribute(attn_kernel, cudaFuncAttributeMaxDynamicSharedMemorySize,
                         (int)smem1);
    cudaFuncSetAttribute(proj_kernel, cudaFuncAttributeMaxDynamicSharedMemorySize,
                         (int)smem2);

    attn_kernel<<<B, 256, smem1>>>(x, mask, qkv_w, bias_table, nW);
    proj_kernel<<<B, 256, smem2>>>(proj_w, proj_b, (float*)d_out);
}

// round 4
// speedup vs baseline: 2.1986x; 2.1986x over previous
#include <cuda_runtime.h>
#include <cuda_bf16.h>
#include <math.h>
#include <stdint.h>

#define NTOK 98
#define CDIM 256
#define NHEAD 8
#define DH 32
#define KPAD 33
#define SPAD 99
#define MAXB 2048

// scratch
__device__ float g_qkv[(size_t)MAXB * NTOK * 3 * CDIM];   // [B,N,768]
__device__ float g_att[(size_t)MAXB * NTOK * CDIM];       // [B,N,256]

extern __shared__ unsigned char smem_raw[];

// ===========================================================================
// mma.sync bf16 helpers
// ===========================================================================
__device__ __forceinline__ uint32_t smem_u32(const void* p) {
    return (uint32_t)__cvta_generic_to_shared(p);
}
__device__ __forceinline__ void ldsm_x4(uint32_t* r, uint32_t a) {
    asm volatile("ldmatrix.sync.aligned.m8n8.x4.shared.b16 {%0,%1,%2,%3},[%4];"
                 : "=r"(r[0]), "=r"(r[1]), "=r"(r[2]), "=r"(r[3]) : "r"(a));
}
__device__ __forceinline__ void ldsm_x4t(uint32_t* r, uint32_t a) {
    asm volatile("ldmatrix.sync.aligned.m8n8.x4.trans.shared.b16 {%0,%1,%2,%3},[%4];"
                 : "=r"(r[0]), "=r"(r[1]), "=r"(r[2]), "=r"(r[3]) : "r"(a));
}
__device__ __forceinline__ void mma16816(float* c, const uint32_t* a,
                                         uint32_t b0, uint32_t b1) {
    asm volatile("mma.sync.aligned.m16n8k16.row.col.f32.bf16.bf16.f32 "
                 "{%0,%1,%2,%3},{%4,%5,%6,%7},{%8,%9},{%0,%1,%2,%3};"
                 : "+f"(c[0]), "+f"(c[1]), "+f"(c[2]), "+f"(c[3])
                 : "r"(a[0]), "r"(a[1]), "r"(a[2]), "r"(a[3]), "r"(b0), "r"(b1));
}

// ===========================================================================
// GEMM  C[M,N] = A[M,K=256] * B[K,N] (+bias), fp32 in/out, bf16x3 core
// BM=128 BN=128 BK=32, 256 threads, warp tile 32x64
// ===========================================================================
#define BM 128
#define BN 128
#define BK 32
#define SA 40      // bf16 row stride of A tiles
#define SB 136     // bf16 row stride of B tiles
#define STAGE_ELEMS (2 * BM * SA + 2 * BK * SB)

static __device__ __forceinline__ void g_load(const float* __restrict__ A,
                                              const float* __restrict__ B,
                                              int M, int N, int m0, int n0, int kt,
                                              int tid, float4* ra, float4* rb) {
    #pragma unroll
    for (int i = 0; i < 4; ++i) {
        int idx = tid + i * 256;
        int r = idx >> 3, c = (idx & 7) << 2;
        int gr = m0 + r; if (gr >= M) gr = M - 1;
        ra[i] = *(const float4*)(A + (size_t)gr * 256 + kt * BK + c);
    }
    #pragma unroll
    for (int i = 0; i < 4; ++i) {
        int idx = tid + i * 256;
        int r = idx >> 5, c = (idx & 31) << 2;
        rb[i] = *(const float4*)(B + (size_t)(kt * BK + r) * N + n0 + c);
    }
}

static __device__ __forceinline__ void g_store(__nv_bfloat16* sm, int s, int tid,
                                               const float4* ra, const float4* rb) {
    __nv_bfloat16* Ah = sm + (size_t)s * STAGE_ELEMS;
    __nv_bfloat16* Al = Ah + BM * SA;
    __nv_bfloat16* Bh = Al + BM * SA;
    __nv_bfloat16* Bl = Bh + BK * SB;
    #pragma unroll
    for (int i = 0; i < 4; ++i) {
        int idx = tid + i * 256;
        int r = idx >> 3, c = (idx & 7) << 2;
        const float* v = (const float*)&ra[i];
        #pragma unroll
        for (int j = 0; j < 4; j += 2) {
            __nv_bfloat16 h0 = __float2bfloat16(v[j]);
            __nv_bfloat16 h1 = __float2bfloat16(v[j + 1]);
            __nv_bfloat16 l0 = __float2bfloat16(v[j]     - __bfloat162float(h0));
            __nv_bfloat16 l1 = __float2bfloat16(v[j + 1] - __bfloat162float(h1));
            *(__nv_bfloat162*)(Ah + r * SA + c + j) = __nv_bfloat162(h0, h1);
            *(__nv_bfloat162*)(Al + r * SA + c + j) = __nv_bfloat162(l0, l1);
        }
    }
    #pragma unroll
    for (int i = 0; i < 4; ++i) {
        int idx = tid + i * 256;
        int r = idx >> 5, c = (idx & 31) << 2;
        const float* v = (const float*)&rb[i];
        #pragma unroll
        for (int j = 0; j < 4; j += 2) {
            __nv_bfloat16 h0 = __float2bfloat16(v[j]);
            __nv_bfloat16 h1 = __float2bfloat16(v[j + 1]);
            __nv_bfloat16 l0 = __float2bfloat16(v[j]     - __bfloat162float(h0));
            __nv_bfloat16 l1 = __float2bfloat16(v[j + 1] - __bfloat162float(h1));
            *(__nv_bfloat162*)(Bh + r * SB + c + j) = __nv_bfloat162(h0, h1);
            *(__nv_bfloat162*)(Bl + r * SB + c + j) = __nv_bfloat162(l0, l1);
        }
    }
}

static __device__ __forceinline__ void g_compute(const __nv_bfloat16* sm, int s,
                                                 int wr, int wc, int lane,
                                                 float acc[2][8][4]) {
    const __nv_bfloat16* Ah = sm + (size_t)s * STAGE_ELEMS;
    const __nv_bfloat16* Al = Ah + BM * SA;
    const __nv_bfloat16* Bh = Al + BM * SA;
    const __nv_bfloat16* Bl = Bh + BK * SB;
    const int sub = lane >> 3, w8 = lane & 7;
    #pragma unroll
    for (int ks = 0; ks < BK; ks += 16) {
        uint32_t ah[2][4], al[2][4], bh[4][4], bl[4][4];
        #pragma unroll
        for (int mf = 0; mf < 2; ++mf) {
            int row = wr + mf * 16 + w8 + (sub & 1) * 8;
            int col = ks + (sub >> 1) * 8;
            ldsm_x4(ah[mf], smem_u32(Ah + row * SA + col));
            ldsm_x4(al[mf], smem_u32(Al + row * SA + col));
        }
        #pragma unroll
        for (int nf = 0; nf < 4; ++nf) {
            int krow = ks + w8 + (sub & 1) * 8;
            int col  = wc + nf * 16 + (sub >> 1) * 8;
            ldsm_x4t(bh[nf], smem_u32(Bh + krow * SB + col));
            ldsm_x4t(bl[nf], smem_u32(Bl + krow * SB + col));
        }
        #pragma unroll
        for (int mf = 0; mf < 2; ++mf)
            #pragma unroll
            for (int nf = 0; nf < 8; ++nf) {
                uint32_t b0h = bh[nf >> 1][(nf & 1) * 2];
                uint32_t b1h = bh[nf >> 1][(nf & 1) * 2 + 1];
                uint32_t b0l = bl[nf >> 1][(nf & 1) * 2];
                uint32_t b1l = bl[nf >> 1][(nf & 1) * 2 + 1];
                mma16816(acc[mf][nf], ah[mf], b0h, b1h);   // hi*hi
                mma16816(acc[mf][nf], ah[mf], b0l, b1l);   // hi*lo
                mma16816(acc[mf][nf], al[mf], b0h, b1h);   // lo*hi
            }
    }
}

__global__ void __launch_bounds__(256, 1)
gemm_bf16x3(const float* __restrict__ A, const float* __restrict__ B,
            const float* __restrict__ bias, float* __restrict__ C,
            int M, int N)
{
    __nv_bfloat16* sm = (__nv_bfloat16*)smem_raw;
    const int tid  = threadIdx.x;
    const int warp = tid >> 5, lane = tid & 31;
    const int m0 = blockIdx.x * BM;
    const int n0 = blockIdx.y * BN;
    const int wr = (warp & 3) * 32;
    const int wc = (warp >> 2) * 64;

    float acc[2][8][4];
    #pragma unroll
    for (int i = 0; i < 2; ++i)
        #pragma unroll
        for (int j = 0; j < 8; ++j)
            #pragma unroll
            for (int k = 0; k < 4; ++k) acc[i][j][k] = 0.f;

    float4 ra[4], rb[4];
    const int NT = 256 / BK;

    g_load(A, B, M, N, m0, n0, 0, tid, ra, rb);
    g_store(sm, 0, tid, ra, rb);
    __syncthreads();

    #pragma unroll 1
    for (int kt = 0; kt < NT; ++kt) {
        bool more = (kt + 1 < NT);
        if (more) g_load(A, B, M, N, m0, n0, kt + 1, tid, ra, rb);
        g_compute(sm, kt & 1, wr, wc, lane, acc);
        if (more) g_store(sm, (kt + 1) & 1, tid, ra, rb);
        __syncthreads();
    }

    const int r4 = lane >> 2, c2 = (lane & 3) * 2;
    #pragma unroll
    for (int mf = 0; mf < 2; ++mf)
        #pragma unroll
        for (int nf = 0; nf < 8; ++nf) {
            int col = n0 + wc + nf * 8 + c2;
            float b0 = bias ? __ldg(bias + col)     : 0.f;
            float b1 = bias ? __ldg(bias + col + 1) : 0.f;
            int row = m0 + wr + mf * 16 + r4;
            if (row < M) {
                float2 v = make_float2(acc[mf][nf][0] + b0, acc[mf][nf][1] + b1);
                *(float2*)(C + (size_t)row * N + col) = v;
            }
            if (row + 8 < M) {
                float2 v = make_float2(acc[mf][nf][2] + b0, acc[mf][nf][3] + b1);
                *(float2*)(C + (size_t)(row + 8) * N + col) = v;
            }
        }
}

// ===========================================================================
// Attention middle: one CTA per (window, head).  fp32.
// ===========================================================================
__global__ void __launch_bounds__(256, 2)
attn2(const float* __restrict__ mask,
      const float* __restrict__ bias_table,
      int nW)
{
    float* q_s = (float*)smem_raw;
    float* k_s = q_s + NTOK * KPAD;
    float* v_s = k_s + NTOK * KPAD;
    float* S   = v_s + NTOK * KPAD;
    int*  base = (int*)(S + NTOK * SPAD);

    const int b   = blockIdx.x >> 3;
    const int h   = blockIdx.x & 7;
    const int tid = threadIdx.x;
    const int wi  = b % nW;
    const float scale = 0.17677669529663689f;

    for (int idx = tid; idx < NTOK * 96; idx += 256) {
        int row = idx / 96, j = idx % 96;
        int grp = j >> 5, jj = j & 31;
        float v = g_qkv[((size_t)b * NTOK + row) * 768 + grp * CDIM + h * DH + jj];
        float* dst = (grp == 0) ? q_s : (grp == 1) ? k_s : v_s;
        dst[row * KPAD + jj] = (grp == 0) ? v * scale : v;
    }
    if (tid < NTOK) {
        int d = tid / 49, rem = tid % 49;
        base[tid] = d * 169 + (rem / 7) * 13 + (rem % 7);
    }
    __syncthreads();

    const int rg   = tid >> 4;
    const int cg   = tid & 15;
    const bool act = (rg < 14);
    const int n0   = rg * 7;
    const int lane = tid & 31;
    const int warp = tid >> 5;

    if (act) {
        float acc[7][7];
        #pragma unroll
        for (int r = 0; r < 7; ++r)
            #pragma unroll
            for (int v = 0; v < 7; ++v) acc[r][v] = 0.f;

        int mm[7];
        #pragma unroll
        for (int v = 0; v < 7; ++v) {
            int m = cg + 16 * v;
            mm[v] = (m < NTOK) ? m : (NTOK - 1);
        }
        #pragma unroll 8
        for (int c = 0; c < DH; ++c) {
            float kv[7], qv[7];
            #pragma unroll
            for (int v = 0; v < 7; ++v) kv[v] = k_s[mm[v] * KPAD + c];
            #pragma unroll
            for (int r = 0; r < 7; ++r) qv[r] = q_s[(n0 + r) * KPAD + c];
            #pragma unroll
            for (int r = 0; r < 7; ++r)
                #pragma unroll
                for (int v = 0; v < 7; ++v)
                    acc[r][v] = fmaf(qv[r], kv[v], acc[r][v]);
        }
        #pragma unroll
        for (int v = 0; v < 7; ++v) {
            int m = cg + 16 * v;
            if (m < NTOK) {
                #pragma unroll
                for (int r = 0; r < 7; ++r) {
                    int n   = n0 + r;
                    int idx = base[n] - base[m] + 253;
                    float bi = __ldg(&bias_table[idx * NHEAD + h]);
                    float mk = __ldg(&mask[((size_t)wi * NTOK + n) * NTOK + m]);
                    S[n * SPAD + m] = acc[r][v] + bi + mk;
                }
            }
        }
    }
    __syncthreads();

    for (int n = warp; n < NTOK; n += 8) {
        float vals[4];
        float mx = -INFINITY;
        #pragma unroll
        for (int k2 = 0; k2 < 4; ++k2) {
            int m = lane + 32 * k2;
            vals[k2] = (m < NTOK) ? S[n * SPAD + m] : -INFINITY;
            mx = fmaxf(mx, vals[k2]);
        }
        #pragma unroll
        for (int o = 16; o > 0; o >>= 1)
            mx = fmaxf(mx, __shfl_xor_sync(0xffffffffu, mx, o));
        float sum = 0.f;
        #pragma unroll
        for (int k2 = 0; k2 < 4; ++k2) {
            int m = lane + 32 * k2;
            if (m < NTOK) { vals[k2] = __expf(vals[k2] - mx); sum += vals[k2]; }
        }
        #pragma unroll
        for (int o = 16; o > 0; o >>= 1)
            sum += __shfl_xor_sync(0xffffffffu, sum, o);
        float inv = __fdividef(1.f, sum);
        #pragma unroll
        for (int k2 = 0; k2 < 4; ++k2) {
            int m = lane + 32 * k2;
            if (m < NTOK) S[n * SPAD + m] = vals[k2] * inv;
        }
    }
    __syncthreads();

    if (act) {
        float a0[7], a1[7];
        #pragma unroll
        for (int r = 0; r < 7; ++r) { a0[r] = 0.f; a1[r] = 0.f; }
        #pragma unroll 2
        for (int m = 0; m < NTOK; ++m) {
            float v0 = v_s[m * KPAD + cg];
            float v1 = v_s[m * KPAD + cg + 16];
            #pragma unroll
            for (int r = 0; r < 7; ++r) {
                float p = S[(n0 + r) * SPAD + m];
                a0[r] = fmaf(p, v0, a0[r]);
                a1[r] = fmaf(p, v1, a1[r]);
            }
        }
        #pragma unroll
        for (int r = 0; r < 7; ++r) {
            int n = n0 + r;
            float* o = g_att + ((size_t)b * NTOK + n) * CDIM + h * DH;
            o[cg]      = a0[r];
            o[cg + 16] = a1[r];
        }
    }
}

// ===========================================================================
extern "C" void kernel_launch(void* const* d_in, const int* in_sizes, int n_in,
                              void* d_out, int out_size)
{
    const float* x          = (const float*)d_in[0];
    const float* mask       = (const float*)d_in[1];
    const float* qkv_w      = (const float*)d_in[2];
    const float* proj_w     = (const float*)d_in[3];
    const float* proj_b     = (const float*)d_in[4];
    const float* bias_table = (const float*)d_in[5];

    int B  = in_sizes[0] / (NTOK * CDIM);
    int nW = in_sizes[1] / (NTOK * NTOK);
    if (B > MAXB) B = MAXB;
    const int M = B * NTOK;

    const size_t smem_g = (size_t)STAGE_ELEMS * 2 * sizeof(__nv_bfloat16);
    const size_t smem_a = (size_t)(3 * NTOK * KPAD + NTOK * SPAD) * 4 + NTOK * 4;

    cudaFuncSetAttribute(gemm_bf16x3, cudaFuncAttributeMaxDynamicSharedMemorySize,
                         (int)smem_g);
    cudaFuncSetAttribute(attn2, cudaFuncAttributeMaxDynamicSharedMemorySize,
                         (int)smem_a);

    void* qkv_ptr = nullptr;
    void* att_ptr = nullptr;
    cudaGetSymbolAddress(&qkv_ptr, g_qkv);
    cudaGetSymbolAddress(&att_ptr, g_att);

    dim3 g1((M + BM - 1) / BM, (3 * CDIM) / BN);
    gemm_bf16x3<<<g1, 256, smem_g>>>(x, qkv_w, nullptr, (float*)qkv_ptr, M, 3 * CDIM);

    attn2<<<B * NHEAD, 256, smem_a>>>(mask, bias_table, nW);

    dim3 g2((M + BM - 1) / BM, CDIM / BN);
    gemm_bf16x3<<<g2, 256, smem_g>>>((float*)att_ptr, proj_w, proj_b,
                                     (float*)d_out, M, CDIM);
}

// round 6
// speedup vs baseline: 2.3006x; 1.0464x over previous
#include <cuda_runtime.h>
#include <cuda_bf16.h>
#include <math.h>
#include <stdint.h>

#define NTOK 98
#define CDIM 256
#define NHEAD 8
#define DH 32
#define KPAD 33
#define SPAD 99
#define MAXB 2048
#define MAXM (MAXB * NTOK)

// scratch (no allocs allowed -> device globals)
__device__ float g_qkv[(size_t)MAXB * NTOK * 3 * CDIM];          // fp32 [B,N,768]
__device__ __nv_bfloat16 g_xh[(size_t)MAXM * CDIM];
__device__ __nv_bfloat16 g_xl[(size_t)MAXM * CDIM];
__device__ __nv_bfloat16 g_ah[(size_t)MAXM * CDIM];              // attn out hi
__device__ __nv_bfloat16 g_al[(size_t)MAXM * CDIM];              // attn out lo
__device__ __nv_bfloat16 g_wqh[CDIM * 3 * CDIM];
__device__ __nv_bfloat16 g_wql[CDIM * 3 * CDIM];
__device__ __nv_bfloat16 g_wph[CDIM * CDIM];
__device__ __nv_bfloat16 g_wpl[CDIM * CDIM];

extern __shared__ unsigned char smem_raw[];

// ===========================================================================
// helpers
// ===========================================================================
__device__ __forceinline__ uint32_t smem_u32(const void* p) {
    return (uint32_t)__cvta_generic_to_shared(p);
}
__device__ __forceinline__ void ldsm_x4(uint32_t* r, uint32_t a) {
    asm volatile("ldmatrix.sync.aligned.m8n8.x4.shared.b16 {%0,%1,%2,%3},[%4];"
                 : "=r"(r[0]), "=r"(r[1]), "=r"(r[2]), "=r"(r[3]) : "r"(a));
}
__device__ __forceinline__ void ldsm_x4t(uint32_t* r, uint32_t a) {
    asm volatile("ldmatrix.sync.aligned.m8n8.x4.trans.shared.b16 {%0,%1,%2,%3},[%4];"
                 : "=r"(r[0]), "=r"(r[1]), "=r"(r[2]), "=r"(r[3]) : "r"(a));
}
__device__ __forceinline__ void mma16816(float* c, const uint32_t* a,
                                         uint32_t b0, uint32_t b1) {
    asm volatile("mma.sync.aligned.m16n8k16.row.col.f32.bf16.bf16.f32 "
                 "{%0,%1,%2,%3},{%4,%5,%6,%7},{%8,%9},{%0,%1,%2,%3};"
                 : "+f"(c[0]), "+f"(c[1]), "+f"(c[2]), "+f"(c[3])
                 : "r"(a[0]), "r"(a[1]), "r"(a[2]), "r"(a[3]), "r"(b0), "r"(b1));
}
#define CP16(dst, src) \
    asm volatile("cp.async.cg.shared.global [%0],[%1],16;" :: "r"(dst), "l"(src))
#define CP_COMMIT() asm volatile("cp.async.commit_group;")
#define CP_WAIT0()  asm volatile("cp.async.wait_group 0;")
#define CP_WAIT1()  asm volatile("cp.async.wait_group 1;")

// fast exp on fma/alu pipes (no MUFU).  x expected <= 0 after max-sub.
__device__ __forceinline__ float fast_exp(float x) {
    x = fmaxf(x, -80.f);
    float t = x * 1.4426950408889634f;          // x * log2(e)
    float r = t + 12582912.f;                   // round to nearest int
    int   k = __float_as_int(r) - 0x4B400000;   // integer part
    float f = t - (r - 12582912.f);             // frac in [-0.5, 0.5]
    float u = f * 0.6931471805599453f;          // |u| <= 0.3466
    float p = 8.3333333e-3f;                    // 1/120
    p = fmaf(p, u, 4.1666667e-2f);              // 1/24
    p = fmaf(p, u, 1.6666667e-1f);              // 1/6
    p = fmaf(p, u, 5.0e-1f);
    p = fmaf(p, u, 1.0f);
    p = fmaf(p, u, 1.0f);
    return p * __int_as_float((k + 127) << 23);
}

// ===========================================================================
// fp32 -> bf16 hi/lo split (vectorized)
// ===========================================================================
__global__ void convert_split(const float* __restrict__ s,
                              __nv_bfloat16* __restrict__ hi,
                              __nv_bfloat16* __restrict__ lo, int n4)
{
    int i = blockIdx.x * blockDim.x + threadIdx.x;
    if (i >= n4) return;
    float4 v = ((const float4*)s)[i];
    __nv_bfloat16 h0 = __float2bfloat16(v.x), h1 = __float2bfloat16(v.y);
    __nv_bfloat16 h2 = __float2bfloat16(v.z), h3 = __float2bfloat16(v.w);
    __nv_bfloat16 l0 = __float2bfloat16(v.x - __bfloat162float(h0));
    __nv_bfloat16 l1 = __float2bfloat16(v.y - __bfloat162float(h1));
    __nv_bfloat16 l2 = __float2bfloat16(v.z - __bfloat162float(h2));
    __nv_bfloat16 l3 = __float2bfloat16(v.w - __bfloat162float(h3));
    ((__nv_bfloat162*)hi)[2 * i]     = __nv_bfloat162(h0, h1);
    ((__nv_bfloat162*)hi)[2 * i + 1] = __nv_bfloat162(h2, h3);
    ((__nv_bfloat162*)lo)[2 * i]     = __nv_bfloat162(l0, l1);
    ((__nv_bfloat162*)lo)[2 * i + 1] = __nv_bfloat162(l2, l3);
}

// ===========================================================================
// GEMM  C[M,N] = A[M,256] * B[256,N] (+bias), bf16x3, cp.async 2-stage
// BM=128 BN=128 BK=32, 256 threads, warp tile 32x64, 2 CTAs/SM
// ===========================================================================
#define BM 128
#define BN 128
#define BK 32
#define SA 40
#define SB 136
#define A_ELEMS (BM * SA)            // per hi/lo matrix
#define B_ELEMS (BK * SB)
#define STAGE_ELEMS (2 * A_ELEMS + 2 * B_ELEMS)   // 18944 bf16

static __device__ __forceinline__ void g2_load(
    const __nv_bfloat16* __restrict__ Ah, const __nv_bfloat16* __restrict__ Al,
    const __nv_bfloat16* __restrict__ Bh, const __nv_bfloat16* __restrict__ Bl,
    __nv_bfloat16* sm, int s, int M, int N, int m0, int n0, int kt, int tid)
{
    __nv_bfloat16* sAh = sm + (size_t)s * STAGE_ELEMS;
    __nv_bfloat16* sAl = sAh + A_ELEMS;
    __nv_bfloat16* sBh = sAl + A_ELEMS;
    __nv_bfloat16* sBl = sBh + B_ELEMS;
    #pragma unroll
    for (int i = 0; i < 2; ++i) {
        int idx = tid + i * 256;
        int row = idx >> 2, ch = (idx & 3) << 3;
        int gr = m0 + row; if (gr >= M) gr = M - 1;
        size_t go = (size_t)gr * 256 + kt * BK + ch;
        uint32_t so = smem_u32(sAh + row * SA + ch);
        CP16(so, Ah + go);
        CP16(so + (uint32_t)(A_ELEMS * 2), Al + go);   // sAl = sAh + A_ELEMS elems
    }
    #pragma unroll
    for (int i = 0; i < 2; ++i) {
        int idx = tid + i * 256;
        int row = idx >> 4, ch = (idx & 15) << 3;
        size_t go = (size_t)(kt * BK + row) * N + n0 + ch;
        uint32_t so = smem_u32(sBh + row * SB + ch);
        CP16(so, Bh + go);
        CP16(so + (uint32_t)(B_ELEMS * 2), Bl + go);
    }
}

static __device__ __forceinline__ void g2_compute(const __nv_bfloat16* sm, int s,
                                                  int wr, int wc, int lane,
                                                  float acc[2][8][4])
{
    const __nv_bfloat16* sAh = sm + (size_t)s * STAGE_ELEMS;
    const __nv_bfloat16* sAl = sAh + A_ELEMS;
    const __nv_bfloat16* sBh = sAl + A_ELEMS;
    const __nv_bfloat16* sBl = sBh + B_ELEMS;
    const int sub = lane >> 3, w8 = lane & 7;
    #pragma unroll
    for (int ks = 0; ks < BK; ks += 16) {
        uint32_t ah[2][4], al[2][4], bh[4][4], bl[4][4];
        #pragma unroll
        for (int mf = 0; mf < 2; ++mf) {
            int row = wr + mf * 16 + w8 + (sub & 1) * 8;
            int col = ks + (sub >> 1) * 8;
            ldsm_x4(ah[mf], smem_u32(sAh + row * SA + col));
            ldsm_x4(al[mf], smem_u32(sAl + row * SA + col));
        }
        #pragma unroll
        for (int nf = 0; nf < 4; ++nf) {
            int krow = ks + w8 + (sub & 1) * 8;
            int col  = wc + nf * 16 + (sub >> 1) * 8;
            ldsm_x4t(bh[nf], smem_u32(sBh + krow * SB + col));
            ldsm_x4t(bl[nf], smem_u32(sBl + krow * SB + col));
        }
        #pragma unroll
        for (int mf = 0; mf < 2; ++mf)
            #pragma unroll
            for (int nf = 0; nf < 8; ++nf) {
                uint32_t b0h = bh[nf >> 1][(nf & 1) * 2];
                uint32_t b1h = bh[nf >> 1][(nf & 1) * 2 + 1];
                uint32_t b0l = bl[nf >> 1][(nf & 1) * 2];
                uint32_t b1l = bl[nf >> 1][(nf & 1) * 2 + 1];
                mma16816(acc[mf][nf], ah[mf], b0h, b1h);
                mma16816(acc[mf][nf], ah[mf], b0l, b1l);
                mma16816(acc[mf][nf], al[mf], b0h, b1h);
            }
    }
}

__global__ void __launch_bounds__(256, 2)
gemm2(const __nv_bfloat16* __restrict__ Ah, const __nv_bfloat16* __restrict__ Al,
      const __nv_bfloat16* __restrict__ Bh, const __nv_bfloat16* __restrict__ Bl,
      const float* __restrict__ bias, float* __restrict__ C, int M, int N)
{
    __nv_bfloat16* sm = (__nv_bfloat16*)smem_raw;
    const int tid  = threadIdx.x;
    const int warp = tid >> 5, lane = tid & 31;
    const int m0 = blockIdx.x * BM;
    const int n0 = blockIdx.y * BN;
    const int wr = (warp & 3) * 32;
    const int wc = (warp >> 2) * 64;

    float acc[2][8][4];
    #pragma unroll
    for (int i = 0; i < 2; ++i)
        #pragma unroll
        for (int j = 0; j < 8; ++j)
            #pragma unroll
            for (int k = 0; k < 4; ++k) acc[i][j][k] = 0.f;

    const int NT = 256 / BK;   // 8

    g2_load(Ah, Al, Bh, Bl, sm, 0, M, N, m0, n0, 0, tid);
    CP_COMMIT();

    #pragma unroll 1
    for (int kt = 0; kt < NT; ++kt) {
        bool more = (kt + 1 < NT);
        if (more) {
            g2_load(Ah, Al, Bh, Bl, sm, (kt + 1) & 1, M, N, m0, n0, kt + 1, tid);
            CP_COMMIT();
            CP_WAIT1();
        } else {
            CP_WAIT0();
        }
        __syncthreads();
        g2_compute(sm, kt & 1, wr, wc, lane, acc);
        __syncthreads();
    }

    const int r4 = lane >> 2, c2 = (lane & 3) * 2;
    #pragma unroll
    for (int mf = 0; mf < 2; ++mf)
        #pragma unroll
        for (int nf = 0; nf < 8; ++nf) {
            int col = n0 + wc + nf * 8 + c2;
            float b0 = bias ? __ldg(bias + col)     : 0.f;
            float b1 = bias ? __ldg(bias + col + 1) : 0.f;
            int row = m0 + wr + mf * 16 + r4;
            if (row < M) {
                float2 v = make_float2(acc[mf][nf][0] + b0, acc[mf][nf][1] + b1);
                *(float2*)(C + (size_t)row * N + col) = v;
            }
            if (row + 8 < M) {
                float2 v = make_float2(acc[mf][nf][2] + b0, acc[mf][nf][3] + b1);
                *(float2*)(C + (size_t)(row + 8) * N + col) = v;
            }
        }
}

// ===========================================================================
// Attention middle: one CTA per (window, head). fp32 math, poly exp,
// writes bf16 hi/lo split output.
// ===========================================================================
__global__ void __launch_bounds__(256, 2)
attn2(const float* __restrict__ mask,
      const float* __restrict__ bias_table,
      int nW)
{
    float* q_s = (float*)smem_raw;
    float* k_s = q_s + NTOK * KPAD;
    float* v_s = k_s + NTOK * KPAD;
    float* S   = v_s + NTOK * KPAD;
    int*  base = (int*)(S + NTOK * SPAD);

    const int b   = blockIdx.x >> 3;
    const int h   = blockIdx.x & 7;
    const int tid = threadIdx.x;
    const int wi  = b % nW;
    const float scale = 0.17677669529663689f;

    for (int idx = tid; idx < NTOK * 96; idx += 256) {
        int row = idx / 96, j = idx % 96;
        int grp = j >> 5, jj = j & 31;
        float v = g_qkv[((size_t)b * NTOK + row) * 768 + grp * CDIM + h * DH + jj];
        float* dst = (grp == 0) ? q_s : (grp == 1) ? k_s : v_s;
        dst[row * KPAD + jj] = (grp == 0) ? v * scale : v;
    }
    if (tid < NTOK) {
        int d = tid / 49, rem = tid % 49;
        base[tid] = d * 169 + (rem / 7) * 13 + (rem % 7);
    }
    __syncthreads();

    const int rg   = tid >> 4;
    const int cg   = tid & 15;
    const bool act = (rg < 14);
    const int n0   = rg * 7;
    const int lane = tid & 31;
    const int warp = tid >> 5;

    if (act) {
        float acc[7][7];
        #pragma unroll
        for (int r = 0; r < 7; ++r)
            #pragma unroll
            for (int v = 0; v < 7; ++v) acc[r][v] = 0.f;

        int mm[7];
        #pragma unroll
        for (int v = 0; v < 7; ++v) {
            int m = cg + 16 * v;
            mm[v] = (m < NTOK) ? m : (NTOK - 1);
        }
        #pragma unroll 8
        for (int c = 0; c < DH; ++c) {
            float kv[7], qv[7];
            #pragma unroll
            for (int v = 0; v < 7; ++v) kv[v] = k_s[mm[v] * KPAD + c];
            #pragma unroll
            for (int r = 0; r < 7; ++r) qv[r] = q_s[(n0 + r) * KPAD + c];
            #pragma unroll
            for (int r = 0; r < 7; ++r)
                #pragma unroll
                for (int v = 0; v < 7; ++v)
                    acc[r][v] = fmaf(qv[r], kv[v], acc[r][v]);
        }
        #pragma unroll
        for (int v = 0; v < 7; ++v) {
            int m = cg + 16 * v;
            if (m < NTOK) {
                #pragma unroll
                for (int r = 0; r < 7; ++r) {
                    int n   = n0 + r;
                    int idx = base[n] - base[m] + 253;
                    float bi = __ldg(&bias_table[idx * NHEAD + h]);
                    float mk = __ldg(&mask[((size_t)wi * NTOK + n) * NTOK + m]);
                    S[n * SPAD + m] = acc[r][v] + bi + mk;
                }
            }
        }
    }
    __syncthreads();

    // softmax (warp per row), MUFU-free exp
    for (int n = warp; n < NTOK; n += 8) {
        float vals[4];
        float mx = -INFINITY;
        #pragma unroll
        for (int k2 = 0; k2 < 4; ++k2) {
            int m = lane + 32 * k2;
            vals[k2] = (m < NTOK) ? S[n * SPAD + m] : -INFINITY;
            mx = fmaxf(mx, vals[k2]);
        }
        #pragma unroll
        for (int o = 16; o > 0; o >>= 1)
            mx = fmaxf(mx, __shfl_xor_sync(0xffffffffu, mx, o));
        float sum = 0.f;
        #pragma unroll
        for (int k2 = 0; k2 < 4; ++k2) {
            int m = lane + 32 * k2;
            if (m < NTOK) { vals[k2] = fast_exp(vals[k2] - mx); sum += vals[k2]; }
        }
        #pragma unroll
        for (int o = 16; o > 0; o >>= 1)
            sum += __shfl_xor_sync(0xffffffffu, sum, o);
        float inv = __fdividef(1.f, sum);
        #pragma unroll
        for (int k2 = 0; k2 < 4; ++k2) {
            int m = lane + 32 * k2;
            if (m < NTOK) S[n * SPAD + m] = vals[k2] * inv;
        }
    }
    __syncthreads();

    if (act) {
        float a0[7], a1[7];
        #pragma unroll
        for (int r = 0; r < 7; ++r) { a0[r] = 0.f; a1[r] = 0.f; }
        #pragma unroll 2
        for (int m = 0; m < NTOK; ++m) {
            float v0 = v_s[m * KPAD + cg];
            float v1 = v_s[m * KPAD + cg + 16];
            #pragma unroll
            for (int r = 0; r < 7; ++r) {
                float p = S[(n0 + r) * SPAD + m];
                a0[r] = fmaf(p, v0, a0[r]);
                a1[r] = fmaf(p, v1, a1[r]);
            }
        }
        #pragma unroll
        for (int r = 0; r < 7; ++r) {
            int n = n0 + r;
            size_t off = ((size_t)b * NTOK + n) * CDIM + h * DH;
            #pragma unroll
            for (int u = 0; u < 2; ++u) {
                float v = u ? a1[r] : a0[r];
                int  c  = cg + 16 * u;
                __nv_bfloat16 hv = __float2bfloat16(v);
                __nv_bfloat16 lv = __float2bfloat16(v - __bfloat162float(hv));
                g_ah[off + c] = hv;
                g_al[off + c] = lv;
            }
        }
    }
}

// ===========================================================================
extern "C" void kernel_launch(void* const* d_in, const int* in_sizes, int n_in,
                              void* d_out, int out_size)
{
    const float* x          = (const float*)d_in[0];
    const float* mask       = (const float*)d_in[1];
    const float* qkv_w      = (const float*)d_in[2];
    const float* proj_w     = (const float*)d_in[3];
    const float* proj_b     = (const float*)d_in[4];
    const float* bias_table = (const float*)d_in[5];

    int B  = in_sizes[0] / (NTOK * CDIM);
    int nW = in_sizes[1] / (NTOK * NTOK);
    if (B > MAXB) B = MAXB;
    const int M = B * NTOK;

    const size_t smem_g = (size_t)STAGE_ELEMS * 2 * sizeof(__nv_bfloat16);
    const size_t smem_a = (size_t)(3 * NTOK * KPAD + NTOK * SPAD) * 4 + NTOK * 4;

    cudaFuncSetAttribute(gemm2, cudaFuncAttributeMaxDynamicSharedMemorySize,
                         (int)smem_g);
    cudaFuncSetAttribute(attn2, cudaFuncAttributeMaxDynamicSharedMemorySize,
                         (int)smem_a);

    void* qkv_p = nullptr; cudaGetSymbolAddress(&qkv_p, g_qkv);
    void* xh_p  = nullptr; cudaGetSymbolAddress(&xh_p,  g_xh);
    void* xl_p  = nullptr; cudaGetSymbolAddress(&xl_p,  g_xl);
    void* ah_p  = nullptr; cudaGetSymbolAddress(&ah_p,  g_ah);
    void* al_p  = nullptr; cudaGetSymbolAddress(&al_p,  g_al);
    void* wqh_p = nullptr; cudaGetSymbolAddress(&wqh_p, g_wqh);
    void* wql_p = nullptr; cudaGetSymbolAddress(&wql_p, g_wql);
    void* wph_p = nullptr; cudaGetSymbolAddress(&wph_p, g_wph);
    void* wpl_p = nullptr; cudaGetSymbolAddress(&wpl_p, g_wpl);

    // split inputs to bf16 hi/lo
    {
        int n4 = M * CDIM / 4;
        convert_split<<<(n4 + 255) / 256, 256>>>(x, (__nv_bfloat16*)xh_p,
                                                 (__nv_bfloat16*)xl_p, n4);
        int w1 = CDIM * 3 * CDIM / 4;
        convert_split<<<(w1 + 255) / 256, 256>>>(qkv_w, (__nv_bfloat16*)wqh_p,
                                                 (__nv_bfloat16*)wql_p, w1);
        int w2 = CDIM * CDIM / 4;
        convert_split<<<(w2 + 255) / 256, 256>>>(proj_w, (__nv_bfloat16*)wph_p,
                                                 (__nv_bfloat16*)wpl_p, w2);
    }

    dim3 g1((M + BM - 1) / BM, (3 * CDIM) / BN);
    gemm2<<<g1, 256, smem_g>>>((__nv_bfloat16*)xh_p, (__nv_bfloat16*)xl_p,
                               (__nv_bfloat16*)wqh_p, (__nv_bfloat16*)wql_p,
                               nullptr, (float*)qkv_p, M, 3 * CDIM);

    attn2<<<B * NHEAD, 256, smem_a>>>(mask, bias_table, nW);

    dim3 g2d((M + BM - 1) / BM, CDIM / BN);
    gemm2<<<g2d, 256, smem_g>>>((__nv_bfloat16*)ah_p, (__nv_bfloat16*)al_p,
                                (__nv_bfloat16*)wph_p, (__nv_bfloat16*)wpl_p,
                                proj_b, (float*)d_out, M, CDIM);
}

// round 9
// speedup vs baseline: 2.5521x; 1.1093x over previous
#include <cuda_runtime.h>
#include <cuda_bf16.h>
#include <math.h>
#include <stdint.h>

#define NTOK 98
#define CDIM 256
#define NHEAD 8
#define DH 32
#define MAXB 2048
#define MAXM (MAXB * NTOK)

// scratch (no allocs allowed -> device globals)
__device__ float g_qkv[(size_t)MAXB * NTOK * 3 * CDIM];          // fp32 [B,N,768]
__device__ __nv_bfloat16 g_xh[(size_t)MAXM * CDIM];
__device__ __nv_bfloat16 g_xl[(size_t)MAXM * CDIM];
__device__ __nv_bfloat16 g_ah[(size_t)MAXM * CDIM];              // attn out hi
__device__ __nv_bfloat16 g_al[(size_t)MAXM * CDIM];              // attn out lo
__device__ __nv_bfloat16 g_wqh[CDIM * 3 * CDIM];
__device__ __nv_bfloat16 g_wql[CDIM * 3 * CDIM];
__device__ __nv_bfloat16 g_wph[CDIM * CDIM];
__device__ __nv_bfloat16 g_wpl[CDIM * CDIM];

extern __shared__ unsigned char smem_raw[];

// ===========================================================================
// helpers
// ===========================================================================
__device__ __forceinline__ uint32_t smem_u32(const void* p) {
    return (uint32_t)__cvta_generic_to_shared(p);
}
__device__ __forceinline__ void ldsm_x4(uint32_t* r, uint32_t a) {
    asm volatile("ldmatrix.sync.aligned.m8n8.x4.shared.b16 {%0,%1,%2,%3},[%4];"
                 : "=r"(r[0]), "=r"(r[1]), "=r"(r[2]), "=r"(r[3]) : "r"(a));
}
__device__ __forceinline__ void ldsm_x4t(uint32_t* r, uint32_t a) {
    asm volatile("ldmatrix.sync.aligned.m8n8.x4.trans.shared.b16 {%0,%1,%2,%3},[%4];"
                 : "=r"(r[0]), "=r"(r[1]), "=r"(r[2]), "=r"(r[3]) : "r"(a));
}
__device__ __forceinline__ void mma16816(float* c, const uint32_t* a,
                                         uint32_t b0, uint32_t b1) {
    asm volatile("mma.sync.aligned.m16n8k16.row.col.f32.bf16.bf16.f32 "
                 "{%0,%1,%2,%3},{%4,%5,%6,%7},{%8,%9},{%0,%1,%2,%3};"
                 : "+f"(c[0]), "+f"(c[1]), "+f"(c[2]), "+f"(c[3])
                 : "r"(a[0]), "r"(a[1]), "r"(a[2]), "r"(a[3]), "r"(b0), "r"(b1));
}
#define CP16(dst, src) \
    asm volatile("cp.async.cg.shared.global [%0],[%1],16;" :: "r"(dst), "l"(src))
#define CP_COMMIT() asm volatile("cp.async.commit_group;")
#define CP_WAIT0()  asm volatile("cp.async.wait_group 0;")
#define CP_WAIT1()  asm volatile("cp.async.wait_group 1;")

// fast exp on fma/alu pipes
__device__ __forceinline__ float fast_exp(float x) {
    x = fmaxf(x, -80.f);
    float t = x * 1.4426950408889634f;
    float r = t + 12582912.f;
    int   k = __float_as_int(r) - 0x4B400000;
    float f = t - (r - 12582912.f);
    float u = f * 0.6931471805599453f;
    float p = 8.3333333e-3f;
    p = fmaf(p, u, 4.1666667e-2f);
    p = fmaf(p, u, 1.6666667e-1f);
    p = fmaf(p, u, 5.0e-1f);
    p = fmaf(p, u, 1.0f);
    p = fmaf(p, u, 1.0f);
    return p * __int_as_float((k + 127) << 23);
}

// split x,y into bf16 hi pair (returned) and lo pair (*lo). low half = x.
__device__ __forceinline__ uint32_t pack_hi_lo(float x, float y, uint32_t* lo) {
    __nv_bfloat16 hx = __float2bfloat16(x), hy = __float2bfloat16(y);
    __nv_bfloat16 lx = __float2bfloat16(x - __bfloat162float(hx));
    __nv_bfloat16 ly = __float2bfloat16(y - __bfloat162float(hy));
    *lo = ((uint32_t)__bfloat16_as_ushort(ly) << 16) | __bfloat16_as_ushort(lx);
    return ((uint32_t)__bfloat16_as_ushort(hy) << 16) | __bfloat16_as_ushort(hx);
}

// ===========================================================================
// fp32 -> bf16 hi/lo split (vectorized)
// ===========================================================================
__global__ void convert_split(const float* __restrict__ s,
                              __nv_bfloat16* __restrict__ hi,
                              __nv_bfloat16* __restrict__ lo, int n4)
{
    int i = blockIdx.x * blockDim.x + threadIdx.x;
    if (i >= n4) return;
    float4 v = ((const float4*)s)[i];
    __nv_bfloat16 h0 = __float2bfloat16(v.x), h1 = __float2bfloat16(v.y);
    __nv_bfloat16 h2 = __float2bfloat16(v.z), h3 = __float2bfloat16(v.w);
    __nv_bfloat16 l0 = __float2bfloat16(v.x - __bfloat162float(h0));
    __nv_bfloat16 l1 = __float2bfloat16(v.y - __bfloat162float(h1));
    __nv_bfloat16 l2 = __float2bfloat16(v.z - __bfloat162float(h2));
    __nv_bfloat16 l3 = __float2bfloat16(v.w - __bfloat162float(h3));
    ((__nv_bfloat162*)hi)[2 * i]     = __nv_bfloat162(h0, h1);
    ((__nv_bfloat162*)hi)[2 * i + 1] = __nv_bfloat162(h2, h3);
    ((__nv_bfloat162*)lo)[2 * i]     = __nv_bfloat162(l0, l1);
    ((__nv_bfloat162*)lo)[2 * i + 1] = __nv_bfloat162(l2, l3);
}

// ===========================================================================
// GEMM  C[M,N] = A[M,256] * B[256,N] (+bias), bf16x3, cp.async 2-stage
// ===========================================================================
#define BM 128
#define BN 128
#define BK 32
#define SA 40
#define SB 136
#define A_ELEMS (BM * SA)
#define B_ELEMS (BK * SB)
#define STAGE_ELEMS (2 * A_ELEMS + 2 * B_ELEMS)

static __device__ __forceinline__ void g2_load(
    const __nv_bfloat16* __restrict__ Ah, const __nv_bfloat16* __restrict__ Al,
    const __nv_bfloat16* __restrict__ Bh, const __nv_bfloat16* __restrict__ Bl,
    __nv_bfloat16* sm, int s, int M, int N, int m0, int n0, int kt, int tid)
{
    __nv_bfloat16* sAh = sm + (size_t)s * STAGE_ELEMS;
    __nv_bfloat16* sBh = sAh + 2 * A_ELEMS;
    #pragma unroll
    for (int i = 0; i < 2; ++i) {
        int idx = tid + i * 256;
        int row = idx >> 2, ch = (idx & 3) << 3;
        int gr = m0 + row; if (gr >= M) gr = M - 1;
        size_t go = (size_t)gr * 256 + kt * BK + ch;
        uint32_t so = smem_u32(sAh + row * SA + ch);
        CP16(so, Ah + go);
        CP16(so + (uint32_t)(A_ELEMS * 2), Al + go);
    }
    #pragma unroll
    for (int i = 0; i < 2; ++i) {
        int idx = tid + i * 256;
        int row = idx >> 4, ch = (idx & 15) << 3;
        size_t go = (size_t)(kt * BK + row) * N + n0 + ch;
        uint32_t so = smem_u32(sBh + row * SB + ch);
        CP16(so, Bh + go);
        CP16(so + (uint32_t)(B_ELEMS * 2), Bl + go);
    }
}

static __device__ __forceinline__ void g2_compute(const __nv_bfloat16* sm, int s,
                                                  int wr, int wc, int lane,
                                                  float acc[2][8][4])
{
    const __nv_bfloat16* sAh = sm + (size_t)s * STAGE_ELEMS;
    const __nv_bfloat16* sAl = sAh + A_ELEMS;
    const __nv_bfloat16* sBh = sAl + A_ELEMS;
    const __nv_bfloat16* sBl = sBh + B_ELEMS;
    const int sub = lane >> 3, w8 = lane & 7;
    #pragma unroll
    for (int ks = 0; ks < BK; ks += 16) {
        uint32_t ah[2][4], al[2][4], bh[4][4], bl[4][4];
        #pragma unroll
        for (int mf = 0; mf < 2; ++mf) {
            int row = wr + mf * 16 + w8 + (sub & 1) * 8;
            int col = ks + (sub >> 1) * 8;
            ldsm_x4(ah[mf], smem_u32(sAh + row * SA + col));
            ldsm_x4(al[mf], smem_u32(sAl + row * SA + col));
        }
        #pragma unroll
        for (int nf = 0; nf < 4; ++nf) {
            int krow = ks + w8 + (sub & 1) * 8;
            int col  = wc + nf * 16 + (sub >> 1) * 8;
            ldsm_x4t(bh[nf], smem_u32(sBh + krow * SB + col));
            ldsm_x4t(bl[nf], smem_u32(sBl + krow * SB + col));
        }
        #pragma unroll
        for (int mf = 0; mf < 2; ++mf)
            #pragma unroll
            for (int nf = 0; nf < 8; ++nf) {
                uint32_t b0h = bh[nf >> 1][(nf & 1) * 2];
                uint32_t b1h = bh[nf >> 1][(nf & 1) * 2 + 1];
                uint32_t b0l = bl[nf >> 1][(nf & 1) * 2];
                uint32_t b1l = bl[nf >> 1][(nf & 1) * 2 + 1];
                mma16816(acc[mf][nf], ah[mf], b0h, b1h);
                mma16816(acc[mf][nf], ah[mf], b0l, b1l);
                mma16816(acc[mf][nf], al[mf], b0h, b1h);
            }
    }
}

__global__ void __launch_bounds__(256, 2)
gemm2(const __nv_bfloat16* __restrict__ Ah, const __nv_bfloat16* __restrict__ Al,
      const __nv_bfloat16* __restrict__ Bh, const __nv_bfloat16* __restrict__ Bl,
      const float* __restrict__ bias, float* __restrict__ C, int M, int N)
{
    __nv_bfloat16* sm = (__nv_bfloat16*)smem_raw;
    const int tid  = threadIdx.x;
    const int warp = tid >> 5, lane = tid & 31;
    const int m0 = blockIdx.x * BM;
    const int n0 = blockIdx.y * BN;
    const int wr = (warp & 3) * 32;
    const int wc = (warp >> 2) * 64;

    float acc[2][8][4];
    #pragma unroll
    for (int i = 0; i < 2; ++i)
        #pragma unroll
        for (int j = 0; j < 8; ++j)
            #pragma unroll
            for (int k = 0; k < 4; ++k) acc[i][j][k] = 0.f;

    const int NT = 256 / BK;

    g2_load(Ah, Al, Bh, Bl, sm, 0, M, N, m0, n0, 0, tid);
    CP_COMMIT();

    #pragma unroll 1
    for (int kt = 0; kt < NT; ++kt) {
        bool more = (kt + 1 < NT);
        if (more) {
            g2_load(Ah, Al, Bh, Bl, sm, (kt + 1) & 1, M, N, m0, n0, kt + 1, tid);
            CP_COMMIT();
            CP_WAIT1();
        } else {
            CP_WAIT0();
        }
        __syncthreads();
        g2_compute(sm, kt & 1, wr, wc, lane, acc);
        __syncthreads();
    }

    const int r4 = lane >> 2, c2 = (lane & 3) * 2;
    #pragma unroll
    for (int mf = 0; mf < 2; ++mf)
        #pragma unroll
        for (int nf = 0; nf < 8; ++nf) {
            int col = n0 + wc + nf * 8 + c2;
            float b0 = bias ? __ldg(bias + col)     : 0.f;
            float b1 = bias ? __ldg(bias + col + 1) : 0.f;
            int row = m0 + wr + mf * 16 + r4;
            if (row < M) {
                float2 v = make_float2(acc[mf][nf][0] + b0, acc[mf][nf][1] + b1);
                *(float2*)(C + (size_t)row * N + col) = v;
            }
            if (row + 8 < M) {
                float2 v = make_float2(acc[mf][nf][2] + b0, acc[mf][nf][3] + b1);
                *(float2*)(C + (size_t)(row + 8) * N + col) = v;
            }
        }
}

// ===========================================================================
// attn3: one CTA (128 thr, 4 warps) per (window, head).  mma-based.
// M pad 128 (32 rows/warp), N pad 112, K=32.  bf16x3 QK^T and PV.
// smem (bf16): qh[128*40] ql[128*40] kh[112*40] kl[112*40] vh[112*40] vl[112*40]
//              + int base[128]   = 56832 B
// ===========================================================================
__global__ void __launch_bounds__(128)
attn3(const float* __restrict__ mask,
      const float* __restrict__ bias_table,
      int nW)
{
    __nv_bfloat16* qh = (__nv_bfloat16*)smem_raw;   // 128x40
    __nv_bfloat16* ql = qh + 5120;
    __nv_bfloat16* kh = ql + 5120;                  // 112x40
    __nv_bfloat16* kl = kh + 4480;
    __nv_bfloat16* vh = kl + 4480;
    __nv_bfloat16* vl = vh + 4480;
    int* base = (int*)(vl + 4480);

    const int b    = blockIdx.x >> 3;
    const int h    = blockIdx.x & 7;
    const int tid  = threadIdx.x;
    const int lane = tid & 31;
    const int warp = tid >> 5;
    const int wi   = b % nW;
    const float scale = 0.17677669529663689f;

    // zero whole tile region (covers all row padding)
    {
        uint32_t* z = (uint32_t*)smem_raw;
        for (int i = tid; i < 14080; i += 128) z[i] = 0;
    }
    __syncthreads();

    // load q,k,v for this (b,h); split hi/lo; q pre-scaled
    for (int idx = tid; idx < NTOK * 96; idx += 128) {
        int row = idx / 96, j = idx % 96;
        int grp = j >> 5, jj = j & 31;
        float v = g_qkv[((size_t)b * NTOK + row) * 768 + grp * 256 + h * 32 + jj];
        if (grp == 0) v *= scale;
        __nv_bfloat16 hv = __float2bfloat16(v);
        __nv_bfloat16 lv = __float2bfloat16(v - __bfloat162float(hv));
        __nv_bfloat16* dh = (grp == 0) ? qh : (grp == 1) ? kh : vh;
        __nv_bfloat16* dl = (grp == 0) ? ql : (grp == 1) ? kl : vl;
        dh[row * 40 + jj] = hv;
        dl[row * 40 + jj] = lv;
    }
    if (tid < 128) {
        int t = (tid < NTOK) ? tid : NTOK - 1;
        int d = t / 49, rem = t % 49;
        base[tid] = d * 169 + (rem / 7) * 13 + (rem % 7);
    }
    __syncthreads();

    const int wr  = warp * 32;
    const int sub = lane >> 3, w8 = lane & 7;
    const int r4  = lane >> 2, c2 = (lane & 3) * 2;

    // ---- S = scale*q k^T  (bf16x3 mma) ------------------------------------
    float S[2][14][4];
    #pragma unroll
    for (int mt = 0; mt < 2; ++mt)
        #pragma unroll
        for (int nt = 0; nt < 14; ++nt)
            #pragma unroll
            for (int i = 0; i < 4; ++i) S[mt][nt][i] = 0.f;

    #pragma unroll
    for (int ks = 0; ks < 2; ++ks) {
        uint32_t aqh[2][4], aql[2][4];
        #pragma unroll
        for (int mt = 0; mt < 2; ++mt) {
            int row = wr + mt * 16 + w8 + (sub & 1) * 8;
            int col = ks * 16 + (sub >> 1) * 8;
            ldsm_x4(aqh[mt], smem_u32(qh + row * 40 + col));
            ldsm_x4(aql[mt], smem_u32(ql + row * 40 + col));
        }
        #pragma unroll
        for (int nt2 = 0; nt2 < 7; ++nt2) {
            uint32_t bkh[4], bkl[4];
            int row = nt2 * 16 + w8 + (sub & 1) * 8;
            int col = ks * 16 + (sub >> 1) * 8;
            ldsm_x4(bkh, smem_u32(kh + row * 40 + col));
            ldsm_x4(bkl, smem_u32(kl + row * 40 + col));
            #pragma unroll
            for (int mt = 0; mt < 2; ++mt) {
                mma16816(S[mt][nt2 * 2],     aqh[mt], bkh[0], bkh[2]);
                mma16816(S[mt][nt2 * 2],     aqh[mt], bkl[0], bkl[2]);
                mma16816(S[mt][nt2 * 2],     aql[mt], bkh[0], bkh[2]);
                mma16816(S[mt][nt2 * 2 + 1], aqh[mt], bkh[1], bkh[3]);
                mma16816(S[mt][nt2 * 2 + 1], aqh[mt], bkl[1], bkl[3]);
                mma16816(S[mt][nt2 * 2 + 1], aql[mt], bkh[1], bkh[3]);
            }
        }
    }

    // ---- + bias + mask, -inf padding ---------------------------------------
    #pragma unroll
    for (int mt = 0; mt < 2; ++mt) {
        #pragma unroll
        for (int half = 0; half < 2; ++half) {
            int row = wr + mt * 16 + r4 + half * 8;
            bool rv = row < NTOK;
            int bn = base[rv ? row : 0];
            const float* mrow = mask + ((size_t)wi * NTOK + (rv ? row : 0)) * NTOK;
            #pragma unroll
            for (int nt = 0; nt < 14; ++nt) {
                #pragma unroll
                for (int i = 0; i < 2; ++i) {
                    int col = nt * 8 + c2 + i;
                    float* sp = &S[mt][nt][half * 2 + i];
                    if (rv && col < NTOK) {
                        int idx = bn - base[col] + 253;
                        *sp += __ldg(&bias_table[idx * NHEAD + h]) + __ldg(&mrow[col]);
                    } else {
                        *sp = -1e9f;
                    }
                }
            }
        }
    }

    // ---- softmax in registers (deferred normalization) ---------------------
    float inv_[2][2];
    #pragma unroll
    for (int mt = 0; mt < 2; ++mt)
        #pragma unroll
        for (int half = 0; half < 2; ++half) {
            float mx = -1e30f;
            #pragma unroll
            for (int nt = 0; nt < 14; ++nt)
                mx = fmaxf(mx, fmaxf(S[mt][nt][half * 2], S[mt][nt][half * 2 + 1]));
            mx = fmaxf(mx, __shfl_xor_sync(0xffffffffu, mx, 1));
            mx = fmaxf(mx, __shfl_xor_sync(0xffffffffu, mx, 2));
            float sum = 0.f;
            #pragma unroll
            for (int nt = 0; nt < 14; ++nt) {
                float e0 = fast_exp(S[mt][nt][half * 2]     - mx);
                float e1 = fast_exp(S[mt][nt][half * 2 + 1] - mx);
                S[mt][nt][half * 2]     = e0;
                S[mt][nt][half * 2 + 1] = e1;
                sum += e0 + e1;
            }
            sum += __shfl_xor_sync(0xffffffffu, sum, 1);
            sum += __shfl_xor_sync(0xffffffffu, sum, 2);
            inv_[mt][half] = __fdividef(1.f, sum);
        }

    // ---- O = P @ V  (bf16x3 mma, P from registers) -------------------------
    float O[2][4][4];
    #pragma unroll
    for (int mt = 0; mt < 2; ++mt)
        #pragma unroll
        for (int nf = 0; nf < 4; ++nf)
            #pragma unroll
            for (int i = 0; i < 4; ++i) O[mt][nf][i] = 0.f;

    #pragma unroll
    for (int kt = 0; kt < 7; ++kt) {
        uint32_t vfh[2][4], vfl[2][4];
        #pragma unroll
        for (int j = 0; j < 2; ++j) {
            int row = kt * 16 + w8 + (sub & 1) * 8;
            int col = j * 16 + (sub >> 1) * 8;
            ldsm_x4t(vfh[j], smem_u32(vh + row * 40 + col));
            ldsm_x4t(vfl[j], smem_u32(vl + row * 40 + col));
        }
        #pragma unroll
        for (int mt = 0; mt < 2; ++mt) {
            const float* cA = S[mt][2 * kt];
            const float* cB = S[mt][2 * kt + 1];
            uint32_t Ph[4], Pl[4];
            Ph[0] = pack_hi_lo(cA[0], cA[1], &Pl[0]);
            Ph[1] = pack_hi_lo(cA[2], cA[3], &Pl[1]);
            Ph[2] = pack_hi_lo(cB[0], cB[1], &Pl[2]);
            Ph[3] = pack_hi_lo(cB[2], cB[3], &Pl[3]);
            #pragma unroll
            for (int nf = 0; nf < 4; ++nf) {
                uint32_t b0h = vfh[nf >> 1][(nf & 1) * 2];
                uint32_t b1h = vfh[nf >> 1][(nf & 1) * 2 + 1];
                uint32_t b0l = vfl[nf >> 1][(nf & 1) * 2];
                uint32_t b1l = vfl[nf >> 1][(nf & 1) * 2 + 1];
                mma16816(O[mt][nf], Ph, b0h, b1h);
                mma16816(O[mt][nf], Ph, b0l, b1l);
                mma16816(O[mt][nf], Pl, b0h, b1h);
            }
        }
    }

    // ---- store (normalize by rowsum, hi/lo split) --------------------------
    #pragma unroll
    for (int mt = 0; mt < 2; ++mt)
        #pragma unroll
        for (int half = 0; half < 2; ++half) {
            int row = wr + mt * 16 + r4 + half * 8;
            if (row < NTOK) {
                float s = inv_[mt][half];
                #pragma unroll
                for (int nf = 0; nf < 4; ++nf)
                    #pragma unroll
                    for (int i = 0; i < 2; ++i) {
                        float v = O[mt][nf][half * 2 + i] * s;
                        int col = h * 32 + nf * 8 + c2 + i;
                        size_t off = ((size_t)b * NTOK + row) * CDIM + col;
                        __nv_bfloat16 hv = __float2bfloat16(v);
                        __nv_bfloat16 lv = __float2bfloat16(v - __bfloat162float(hv));
                        g_ah[off] = hv;
                        g_al[off] = lv;
                    }
            }
        }
}

// ===========================================================================
extern "C" void kernel_launch(void* const* d_in, const int* in_sizes, int n_in,
                              void* d_out, int out_size)
{
    const float* x          = (const float*)d_in[0];
    const float* mask       = (const float*)d_in[1];
    const float* qkv_w      = (const float*)d_in[2];
    const float* proj_w     = (const float*)d_in[3];
    const float* proj_b     = (const float*)d_in[4];
    const float* bias_table = (const float*)d_in[5];

    int B  = in_sizes[0] / (NTOK * CDIM);
    int nW = in_sizes[1] / (NTOK * NTOK);
    if (B > MAXB) B = MAXB;
    const int M = B * NTOK;

    const size_t smem_g = (size_t)STAGE_ELEMS * 2 * sizeof(__nv_bfloat16);
    const size_t smem_a = 56832;

    cudaFuncSetAttribute(gemm2, cudaFuncAttributeMaxDynamicSharedMemorySize,
                         (int)smem_g);
    cudaFuncSetAttribute(attn3, cudaFuncAttributeMaxDynamicSharedMemorySize,
                         (int)smem_a);

    void* qkv_p = nullptr; cudaGetSymbolAddress(&qkv_p, g_qkv);
    void* xh_p  = nullptr; cudaGetSymbolAddress(&xh_p,  g_xh);
    void* xl_p  = nullptr; cudaGetSymbolAddress(&xl_p,  g_xl);
    void* ah_p  = nullptr; cudaGetSymbolAddress(&ah_p,  g_ah);
    void* al_p  = nullptr; cudaGetSymbolAddress(&al_p,  g_al);
    void* wqh_p = nullptr; cudaGetSymbolAddress(&wqh_p, g_wqh);
    void* wql_p = nullptr; cudaGetSymbolAddress(&wql_p, g_wql);
    void* wph_p = nullptr; cudaGetSymbolAddress(&wph_p, g_wph);
    void* wpl_p = nullptr; cudaGetSymbolAddress(&wpl_p, g_wpl);

    {
        int n4 = M * CDIM / 4;
        convert_split<<<(n4 + 255) / 256, 256>>>(x, (__nv_bfloat16*)xh_p,
                                                 (__nv_bfloat16*)xl_p, n4);
        int w1 = CDIM * 3 * CDIM / 4;
        convert_split<<<(w1 + 255) / 256, 256>>>(qkv_w, (__nv_bfloat16*)wqh_p,
                                                 (__nv_bfloat16*)wql_p, w1);
        int w2 = CDIM * CDIM / 4;
        convert_split<<<(w2 + 255) / 256, 256>>>(proj_w, (__nv_bfloat16*)wph_p,
                                                 (__nv_bfloat16*)wpl_p, w2);
    }

    dim3 g1((M + BM - 1) / BM, (3 * CDIM) / BN);
    gemm2<<<g1, 256, smem_g>>>((__nv_bfloat16*)xh_p, (__nv_bfloat16*)xl_p,
                               (__nv_bfloat16*)wqh_p, (__nv_bfloat16*)wql_p,
                               nullptr, (float*)qkv_p, M, 3 * CDIM);

    attn3<<<B * NHEAD, 128, smem_a>>>(mask, bias_table, nW);

    dim3 g2d((M + BM - 1) / BM, CDIM / BN);
    gemm2<<<g2d, 256, smem_g>>>((__nv_bfloat16*)ah_p, (__nv_bfloat16*)al_p,
                                (__nv_bfloat16*)wph_p, (__nv_bfloat16*)wpl_p,
                                proj_b, (float*)d_out, M, CDIM);
}

// round 12
// speedup vs baseline: 3.8462x; 1.5071x over previous
#include <cuda_runtime.h>
#include <cuda_bf16.h>
#include <math.h>
#include <stdint.h>

#define NTOK 98
#define CDIM 256
#define NHEAD 8
#define DH 32
#define MAXB 2048
#define MAXM (MAXB * NTOK)
#define MAXNW 64

// scratch (no allocs allowed -> device globals)
__device__ __nv_bfloat16 g_xh[(size_t)MAXM * CDIM];
__device__ __nv_bfloat16 g_xl[(size_t)MAXM * CDIM];
__device__ __nv_bfloat16 g_qkvh[(size_t)MAXM * 3 * CDIM];   // qkv hi [B*N,768]
__device__ __nv_bfloat16 g_qkvl[(size_t)MAXM * 3 * CDIM];   // qkv lo
__device__ __nv_bfloat16 g_ah[(size_t)MAXM * CDIM];         // attn out hi
__device__ __nv_bfloat16 g_al[(size_t)MAXM * CDIM];         // attn out lo
__device__ __nv_bfloat16 g_wqh[CDIM * 3 * CDIM];
__device__ __nv_bfloat16 g_wql[CDIM * 3 * CDIM];
__device__ __nv_bfloat16 g_wph[CDIM * CDIM];
__device__ __nv_bfloat16 g_wpl[CDIM * CDIM];
__device__ float g_bm[(size_t)MAXNW * NHEAD * NTOK * 100];  // bias+mask slabs

extern __shared__ unsigned char smem_raw[];

// ===========================================================================
// helpers
// ===========================================================================
__device__ __forceinline__ uint32_t smem_u32(const void* p) {
    return (uint32_t)__cvta_generic_to_shared(p);
}
__device__ __forceinline__ void ldsm_x4(uint32_t* r, uint32_t a) {
    asm volatile("ldmatrix.sync.aligned.m8n8.x4.shared.b16 {%0,%1,%2,%3},[%4];"
                 : "=r"(r[0]), "=r"(r[1]), "=r"(r[2]), "=r"(r[3]) : "r"(a));
}
__device__ __forceinline__ void ldsm_x4t(uint32_t* r, uint32_t a) {
    asm volatile("ldmatrix.sync.aligned.m8n8.x4.trans.shared.b16 {%0,%1,%2,%3},[%4];"
                 : "=r"(r[0]), "=r"(r[1]), "=r"(r[2]), "=r"(r[3]) : "r"(a));
}
__device__ __forceinline__ void mma16816(float* c, const uint32_t* a,
                                         uint32_t b0, uint32_t b1) {
    asm volatile("mma.sync.aligned.m16n8k16.row.col.f32.bf16.bf16.f32 "
                 "{%0,%1,%2,%3},{%4,%5,%6,%7},{%8,%9},{%0,%1,%2,%3};"
                 : "+f"(c[0]), "+f"(c[1]), "+f"(c[2]), "+f"(c[3])
                 : "r"(a[0]), "r"(a[1]), "r"(a[2]), "r"(a[3]), "r"(b0), "r"(b1));
}
#define CP16(dst, src) \
    asm volatile("cp.async.cg.shared.global [%0],[%1],16;" :: "r"(dst), "l"(src))
#define CP_COMMIT() asm volatile("cp.async.commit_group;")
#define CP_WAIT0()  asm volatile("cp.async.wait_group 0;")
#define CP_WAIT1()  asm volatile("cp.async.wait_group 1;")

// fast exp on fma/alu pipes
__device__ __forceinline__ float fast_exp(float x) {
    x = fmaxf(x, -80.f);
    float t = x * 1.4426950408889634f;
    float r = t + 12582912.f;
    int   k = __float_as_int(r) - 0x4B400000;
    float f = t - (r - 12582912.f);
    float u = f * 0.6931471805599453f;
    float p = 8.3333333e-3f;
    p = fmaf(p, u, 4.1666667e-2f);
    p = fmaf(p, u, 1.6666667e-1f);
    p = fmaf(p, u, 5.0e-1f);
    p = fmaf(p, u, 1.0f);
    p = fmaf(p, u, 1.0f);
    return p * __int_as_float((k + 127) << 23);
}

// split x,y -> packed bf16 hi pair (return) + lo pair (*lo); low 16 bits = x
__device__ __forceinline__ uint32_t pack_hi_lo(float x, float y, uint32_t* lo) {
    __nv_bfloat16 hx = __float2bfloat16(x), hy = __float2bfloat16(y);
    __nv_bfloat16 lx = __float2bfloat16(x - __bfloat162float(hx));
    __nv_bfloat16 ly = __float2bfloat16(y - __bfloat162float(hy));
    *lo = ((uint32_t)__bfloat16_as_ushort(ly) << 16) | __bfloat16_as_ushort(lx);
    return ((uint32_t)__bfloat16_as_ushort(hy) << 16) | __bfloat16_as_ushort(hx);
}

__device__ __forceinline__ int rel_base(int t) {
    int d = t / 49, rem = t % 49;
    return d * 169 + (rem / 7) * 13 + (rem % 7);
}

// ===========================================================================
// fp32 -> bf16 hi/lo split; cols < nscale4 float4-groups of each row get *scale
// ===========================================================================
__global__ void convert_split(const float* __restrict__ s,
                              __nv_bfloat16* __restrict__ hi,
                              __nv_bfloat16* __restrict__ lo,
                              int n4, int width4, int nscale4, float scale)
{
    int i = blockIdx.x * blockDim.x + threadIdx.x;
    if (i >= n4) return;
    float4 v = ((const float4*)s)[i];
    float sc = ((i % width4) < nscale4) ? scale : 1.f;
    v.x *= sc; v.y *= sc; v.z *= sc; v.w *= sc;
    __nv_bfloat16 h0 = __float2bfloat16(v.x), h1 = __float2bfloat16(v.y);
    __nv_bfloat16 h2 = __float2bfloat16(v.z), h3 = __float2bfloat16(v.w);
    __nv_bfloat16 l0 = __float2bfloat16(v.x - __bfloat162float(h0));
    __nv_bfloat16 l1 = __float2bfloat16(v.y - __bfloat162float(h1));
    __nv_bfloat16 l2 = __float2bfloat16(v.z - __bfloat162float(h2));
    __nv_bfloat16 l3 = __float2bfloat16(v.w - __bfloat162float(h3));
    ((__nv_bfloat162*)hi)[2 * i]     = __nv_bfloat162(h0, h1);
    ((__nv_bfloat162*)hi)[2 * i + 1] = __nv_bfloat162(h2, h3);
    ((__nv_bfloat162*)lo)[2 * i]     = __nv_bfloat162(l0, l1);
    ((__nv_bfloat162*)lo)[2 * i + 1] = __nv_bfloat162(l2, l3);
}

// ===========================================================================
// bm[wi][h][n][m(pad 100)] = bias_table[relidx(n,m)][h] + mask[wi][n][m]
// ===========================================================================
__global__ void prep_bm(const float* __restrict__ mask,
                        const float* __restrict__ bias_table, int nW)
{
    int idx = blockIdx.x * blockDim.x + threadIdx.x;
    int total = nW * NHEAD * NTOK * 100;
    if (idx >= total) return;
    int m  = idx % 100;
    int n  = (idx / 100) % NTOK;
    int h  = (idx / (100 * NTOK)) % NHEAD;
    int wi = idx / (100 * NTOK * NHEAD);
    float v = 0.f;
    if (m < NTOK) {
        int ri = rel_base(n) - rel_base(m) + 253;
        v = __ldg(&bias_table[ri * NHEAD + h])
          + __ldg(&mask[((size_t)wi * NTOK + n) * NTOK + m]);
    }
    g_bm[idx] = v;
}

// ===========================================================================
// GEMM core: bf16x3, cp.async 2-stage.  BM=128 BN=128 BK=32, 256 thr.
// ===========================================================================
#define BM 128
#define BN 128
#define BK 32
#define SA 40
#define SB 136
#define A_ELEMS (BM * SA)
#define B_ELEMS (BK * SB)
#define STAGE_ELEMS (2 * A_ELEMS + 2 * B_ELEMS)

static __device__ __forceinline__ void g2_load(
    const __nv_bfloat16* __restrict__ Ah, const __nv_bfloat16* __restrict__ Al,
    const __nv_bfloat16* __restrict__ Bh, const __nv_bfloat16* __restrict__ Bl,
    __nv_bfloat16* sm, int s, int M, int N, int m0, int n0, int kt, int tid)
{
    __nv_bfloat16* sAh = sm + (size_t)s * STAGE_ELEMS;
    __nv_bfloat16* sBh = sAh + 2 * A_ELEMS;
    #pragma unroll
    for (int i = 0; i < 2; ++i) {
        int idx = tid + i * 256;
        int row = idx >> 2, ch = (idx & 3) << 3;
        int gr = m0 + row; if (gr >= M) gr = M - 1;
        size_t go = (size_t)gr * 256 + kt * BK + ch;
        uint32_t so = smem_u32(sAh + row * SA + ch);
        CP16(so, Ah + go);
        CP16(so + (uint32_t)(A_ELEMS * 2), Al + go);
    }
    #pragma unroll
    for (int i = 0; i < 2; ++i) {
        int idx = tid + i * 256;
        int row = idx >> 4, ch = (idx & 15) << 3;
        size_t go = (size_t)(kt * BK + row) * N + n0 + ch;
        uint32_t so = smem_u32(sBh + row * SB + ch);
        CP16(so, Bh + go);
        CP16(so + (uint32_t)(B_ELEMS * 2), Bl + go);
    }
}

static __device__ __forceinline__ void g2_compute(const __nv_bfloat16* sm, int s,
                                                  int wr, int wc, int lane,
                                                  float acc[2][8][4])
{
    const __nv_bfloat16* sAh = sm + (size_t)s * STAGE_ELEMS;
    const __nv_bfloat16* sAl = sAh + A_ELEMS;
    const __nv_bfloat16* sBh = sAl + A_ELEMS;
    const __nv_bfloat16* sBl = sBh + B_ELEMS;
    const int sub = lane >> 3, w8 = lane & 7;
    #pragma unroll
    for (int ks = 0; ks < BK; ks += 16) {
        uint32_t ah[2][4], al[2][4], bh[4][4], bl[4][4];
        #pragma unroll
        for (int mf = 0; mf < 2; ++mf) {
            int row = wr + mf * 16 + w8 + (sub & 1) * 8;
            int col = ks + (sub >> 1) * 8;
            ldsm_x4(ah[mf], smem_u32(sAh + row * SA + col));
            ldsm_x4(al[mf], smem_u32(sAl + row * SA + col));
        }
        #pragma unroll
        for (int nf = 0; nf < 4; ++nf) {
            int krow = ks + w8 + (sub & 1) * 8;
            int col  = wc + nf * 16 + (sub >> 1) * 8;
            ldsm_x4t(bh[nf], smem_u32(sBh + krow * SB + col));
            ldsm_x4t(bl[nf], smem_u32(sBl + krow * SB + col));
        }
        #pragma unroll
        for (int mf = 0; mf < 2; ++mf)
            #pragma unroll
            for (int nf = 0; nf < 8; ++nf) {
                uint32_t b0h = bh[nf >> 1][(nf & 1) * 2];
                uint32_t b1h = bh[nf >> 1][(nf & 1) * 2 + 1];
                uint32_t b0l = bl[nf >> 1][(nf & 1) * 2];
                uint32_t b1l = bl[nf >> 1][(nf & 1) * 2 + 1];
                mma16816(acc[mf][nf], ah[mf], b0h, b1h);
                mma16816(acc[mf][nf], ah[mf], b0l, b1l);
                mma16816(acc[mf][nf], al[mf], b0h, b1h);
            }
    }
}

// mainloop shared by both gemm kernels
#define G2_MAINLOOP()                                                        \
    float acc[2][8][4];                                                      \
    _Pragma("unroll")                                                        \
    for (int i = 0; i < 2; ++i)                                              \
        _Pragma("unroll")                                                    \
        for (int j = 0; j < 8; ++j)                                          \
            _Pragma("unroll")                                                \
            for (int k = 0; k < 4; ++k) acc[i][j][k] = 0.f;                  \
    const int NT = 256 / BK;                                                 \
    g2_load(Ah, Al, Bh, Bl, sm, 0, M, N, m0, n0, 0, tid);                    \
    CP_COMMIT();                                                             \
    _Pragma("unroll 1")                                                      \
    for (int kt = 0; kt < NT; ++kt) {                                        \
        bool more = (kt + 1 < NT);                                           \
        if (more) {                                                          \
            g2_load(Ah, Al, Bh, Bl, sm, (kt + 1) & 1, M, N, m0, n0, kt + 1, tid); \
            CP_COMMIT();                                                     \
            CP_WAIT1();                                                      \
        } else {                                                             \
            CP_WAIT0();                                                      \
        }                                                                    \
        __syncthreads();                                                     \
        g2_compute(sm, kt & 1, wr, wc, lane, acc);                           \
        __syncthreads();                                                     \
    }

// fp32 output + bias (proj path)
__global__ void __launch_bounds__(256, 2)
gemm2(const __nv_bfloat16* __restrict__ Ah, const __nv_bfloat16* __restrict__ Al,
      const __nv_bfloat16* __restrict__ Bh, const __nv_bfloat16* __restrict__ Bl,
      const float* __restrict__ bias, float* __restrict__ C, int M, int N)
{
    __nv_bfloat16* sm = (__nv_bfloat16*)smem_raw;
    const int tid  = threadIdx.x;
    const int warp = tid >> 5, lane = tid & 31;
    const int m0 = blockIdx.x * BM;
    const int n0 = blockIdx.y * BN;
    const int wr = (warp & 3) * 32;
    const int wc = (warp >> 2) * 64;

    G2_MAINLOOP();

    const int r4 = lane >> 2, c2 = (lane & 3) * 2;
    #pragma unroll
    for (int mf = 0; mf < 2; ++mf)
        #pragma unroll
        for (int nf = 0; nf < 8; ++nf) {
            int col = n0 + wc + nf * 8 + c2;
            float b0 = __ldg(bias + col);
            float b1 = __ldg(bias + col + 1);
            int row = m0 + wr + mf * 16 + r4;
            if (row < M) {
                float2 v = make_float2(acc[mf][nf][0] + b0, acc[mf][nf][1] + b1);
                *(float2*)(C + (size_t)row * N + col) = v;
            }
            if (row + 8 < M) {
                float2 v = make_float2(acc[mf][nf][2] + b0, acc[mf][nf][3] + b1);
                *(float2*)(C + (size_t)(row + 8) * N + col) = v;
            }
        }
}

// bf16 hi/lo split output, no bias (qkv path)
__global__ void __launch_bounds__(256, 2)
gemm2b(const __nv_bfloat16* __restrict__ Ah, const __nv_bfloat16* __restrict__ Al,
       const __nv_bfloat16* __restrict__ Bh, const __nv_bfloat16* __restrict__ Bl,
       __nv_bfloat16* __restrict__ Ch, __nv_bfloat16* __restrict__ Cl,
       int M, int N)
{
    __nv_bfloat16* sm = (__nv_bfloat16*)smem_raw;
    const int tid  = threadIdx.x;
    const int warp = tid >> 5, lane = tid & 31;
    const int m0 = blockIdx.x * BM;
    const int n0 = blockIdx.y * BN;
    const int wr = (warp & 3) * 32;
    const int wc = (warp >> 2) * 64;

    G2_MAINLOOP();

    const int r4 = lane >> 2, c2 = (lane & 3) * 2;
    #pragma unroll
    for (int mf = 0; mf < 2; ++mf)
        #pragma unroll
        for (int nf = 0; nf < 8; ++nf) {
            int col = n0 + wc + nf * 8 + c2;
            int row = m0 + wr + mf * 16 + r4;
            if (row < M) {
                uint32_t lo, hi = pack_hi_lo(acc[mf][nf][0], acc[mf][nf][1], &lo);
                *(uint32_t*)(Ch + (size_t)row * N + col) = hi;
                *(uint32_t*)(Cl + (size_t)row * N + col) = lo;
            }
            if (row + 8 < M) {
                uint32_t lo, hi = pack_hi_lo(acc[mf][nf][2], acc[mf][nf][3], &lo);
                *(uint32_t*)(Ch + (size_t)(row + 8) * N + col) = hi;
                *(uint32_t*)(Cl + (size_t)(row + 8) * N + col) = lo;
            }
        }
}

// ===========================================================================
// attn4: one CTA (128 thr) per (window, head). cp.async prologue, mma core,
// smem bm slab. smem: q[128x40]h/l k[112x40]h/l v[112x40]h/l bf16 + bm f32[98x100]
// ===========================================================================
__global__ void __launch_bounds__(128, 2)
attn4(const __nv_bfloat16* __restrict__ Qh, const __nv_bfloat16* __restrict__ Ql,
      int nW)
{
    __nv_bfloat16* qh = (__nv_bfloat16*)smem_raw;   // 128x40
    __nv_bfloat16* ql = qh + 5120;
    __nv_bfloat16* kh = ql + 5120;                  // 112x40
    __nv_bfloat16* kl = kh + 4480;
    __nv_bfloat16* vh = kl + 4480;
    __nv_bfloat16* vl = vh + 4480;
    float* bm_s = (float*)(vl + 4480);              // 98x100

    const int b    = blockIdx.x >> 3;
    const int h    = blockIdx.x & 7;
    const int tid  = threadIdx.x;
    const int lane = tid & 31;
    const int warp = tid >> 5;
    const int wi   = b % nW;

    // zero V padding rows 98..111 (hi+lo) — only place garbage could leak via PV
    {
        uint32_t* zv = (uint32_t*)(vh + 98 * 40);
        uint32_t* zl = (uint32_t*)(vl + 98 * 40);
        for (int i = tid; i < 280; i += 128) { zv[i] = 0; zl[i] = 0; }
    }

    // cp.async: q/k/v hi+lo slabs (32 cols of head h)
    {
        __nv_bfloat16* mats[6] = {qh, ql, kh, kl, vh, vl};
        for (int idx = tid; idx < 2352; idx += 128) {
            int chunk = idx & 3;
            int row   = (idx >> 2) % 98;
            int mat   = idx / 392;
            int grp   = mat >> 1;
            const __nv_bfloat16* src = (mat & 1) ? Ql : Qh;
            size_t go = ((size_t)b * NTOK + row) * 768 + grp * 256 + h * 32 + chunk * 8;
            CP16(smem_u32(mats[mat] + row * 40 + chunk * 8), src + go);
        }
        const float* slab = g_bm + (size_t)(wi * NHEAD + h) * (NTOK * 100);
        for (int idx = tid; idx < 2450; idx += 128)
            CP16(smem_u32(bm_s + idx * 4), slab + idx * 4);
    }
    CP_COMMIT();
    CP_WAIT0();
    __syncthreads();

    const int wr  = warp * 32;
    const int sub = lane >> 3, w8 = lane & 7;
    const int r4  = lane >> 2, c2 = (lane & 3) * 2;

    // ---- S = q k^T (scale pre-folded into Wq), bf16x3 ----------------------
    float S[2][14][4];
    #pragma unroll
    for (int mt = 0; mt < 2; ++mt)
        #pragma unroll
        for (int nt = 0; nt < 14; ++nt)
            #pragma unroll
            for (int i = 0; i < 4; ++i) S[mt][nt][i] = 0.f;

    #pragma unroll
    for (int ks = 0; ks < 2; ++ks) {
        uint32_t aqh[2][4], aql[2][4];
        #pragma unroll
        for (int mt = 0; mt < 2; ++mt) {
            int row = wr + mt * 16 + w8 + (sub & 1) * 8;
            int col = ks * 16 + (sub >> 1) * 8;
            ldsm_x4(aqh[mt], smem_u32(qh + row * 40 + col));
            ldsm_x4(aql[mt], smem_u32(ql + row * 40 + col));
        }
        #pragma unroll
        for (int nt2 = 0; nt2 < 7; ++nt2) {
            uint32_t bkh[4], bkl[4];
            int row = nt2 * 16 + w8 + (sub & 1) * 8;
            int col = ks * 16 + (sub >> 1) * 8;
            ldsm_x4(bkh, smem_u32(kh + row * 40 + col));
            ldsm_x4(bkl, smem_u32(kl + row * 40 + col));
            #pragma unroll
            for (int mt = 0; mt < 2; ++mt) {
                mma16816(S[mt][nt2 * 2],     aqh[mt], bkh[0], bkh[2]);
                mma16816(S[mt][nt2 * 2],     aqh[mt], bkl[0], bkl[2]);
                mma16816(S[mt][nt2 * 2],     aql[mt], bkh[0], bkh[2]);
                mma16816(S[mt][nt2 * 2 + 1], aqh[mt], bkh[1], bkh[3]);
                mma16816(S[mt][nt2 * 2 + 1], aqh[mt], bkl[1], bkl[3]);
                mma16816(S[mt][nt2 * 2 + 1], aql[mt], bkh[1], bkh[3]);
            }
        }
    }

    // ---- + (bias+mask) from smem slab, -1e9 padding ------------------------
    #pragma unroll
    for (int mt = 0; mt < 2; ++mt) {
        #pragma unroll
        for (int half = 0; half < 2; ++half) {
            int row = wr + mt * 16 + r4 + half * 8;
            bool rv = row < NTOK;
            const float* bmrow = bm_s + (rv ? row : 0) * 100;
            #pragma unroll
            for (int nt = 0; nt < 14; ++nt) {
                int col = nt * 8 + c2;
                float* sp = &S[mt][nt][half * 2];
                if (rv && col < NTOK) {
                    float2 bm2 = *(const float2*)(bmrow + col);
                    sp[0] += bm2.x;
                    sp[1] += bm2.y;
                } else {
                    sp[0] = -1e9f;
                    sp[1] = -1e9f;
                }
            }
        }
    }

    // ---- softmax in registers (deferred normalization) ---------------------
    float inv_[2][2];
    #pragma unroll
    for (int mt = 0; mt < 2; ++mt)
        #pragma unroll
        for (int half = 0; half < 2; ++half) {
            float mx = -1e30f;
            #pragma unroll
            for (int nt = 0; nt < 14; ++nt)
                mx = fmaxf(mx, fmaxf(S[mt][nt][half * 2], S[mt][nt][half * 2 + 1]));
            mx = fmaxf(mx, __shfl_xor_sync(0xffffffffu, mx, 1));
            mx = fmaxf(mx, __shfl_xor_sync(0xffffffffu, mx, 2));
            float sum = 0.f;
            #pragma unroll
            for (int nt = 0; nt < 14; ++nt) {
                float e0 = fast_exp(S[mt][nt][half * 2]     - mx);
                float e1 = fast_exp(S[mt][nt][half * 2 + 1] - mx);
                S[mt][nt][half * 2]     = e0;
                S[mt][nt][half * 2 + 1] = e1;
                sum += e0 + e1;
            }
            sum += __shfl_xor_sync(0xffffffffu, sum, 1);
            sum += __shfl_xor_sync(0xffffffffu, sum, 2);
            inv_[mt][half] = __fdividef(1.f, sum);
        }

    // ---- O = P @ V (bf16x3) ------------------------------------------------
    float O[2][4][4];
    #pragma unroll
    for (int mt = 0; mt < 2; ++mt)
        #pragma unroll
        for (int nf = 0; nf < 4; ++nf)
            #pragma unroll
            for (int i = 0; i < 4; ++i) O[mt][nf][i] = 0.f;

    #pragma unroll
    for (int kt = 0; kt < 7; ++kt) {
        uint32_t vfh[2][4], vfl[2][4];
        #pragma unroll
        for (int j = 0; j < 2; ++j) {
            int row = kt * 16 + w8 + (sub & 1) * 8;
            int col = j * 16 + (sub >> 1) * 8;
            ldsm_x4t(vfh[j], smem_u32(vh + row * 40 + col));
            ldsm_x4t(vfl[j], smem_u32(vl + row * 40 + col));
        }
        #pragma unroll
        for (int mt = 0; mt < 2; ++mt) {
            const float* cA = S[mt][2 * kt];
            const float* cB = S[mt][2 * kt + 1];
            uint32_t Ph[4], Pl[4];
            Ph[0] = pack_hi_lo(cA[0], cA[1], &Pl[0]);
            Ph[1] = pack_hi_lo(cA[2], cA[3], &Pl[1]);
            Ph[2] = pack_hi_lo(cB[0], cB[1], &Pl[2]);
            Ph[3] = pack_hi_lo(cB[2], cB[3], &Pl[3]);
            #pragma unroll
            for (int nf = 0; nf < 4; ++nf) {
                uint32_t b0h = vfh[nf >> 1][(nf & 1) * 2];
                uint32_t b1h = vfh[nf >> 1][(nf & 1) * 2 + 1];
                uint32_t b0l = vfl[nf >> 1][(nf & 1) * 2];
                uint32_t b1l = vfl[nf >> 1][(nf & 1) * 2 + 1];
                mma16816(O[mt][nf], Ph, b0h, b1h);
                mma16816(O[mt][nf], Ph, b0l, b1l);
                mma16816(O[mt][nf], Pl, b0h, b1h);
            }
        }
    }

    // ---- store normalized, hi/lo split, vectorized -------------------------
    #pragma unroll
    for (int mt = 0; mt < 2; ++mt)
        #pragma unroll
        for (int half = 0; half < 2; ++half) {
            int row = wr + mt * 16 + r4 + half * 8;
            if (row < NTOK) {
                float s = inv_[mt][half];
                #pragma unroll
                for (int nf = 0; nf < 4; ++nf) {
                    float v0 = O[mt][nf][half * 2]     * s;
                    float v1 = O[mt][nf][half * 2 + 1] * s;
                    int col = h * 32 + nf * 8 + c2;
                    size_t off = ((size_t)b * NTOK + row) * CDIM + col;
                    uint32_t lo, hi = pack_hi_lo(v0, v1, &lo);
                    *(uint32_t*)(g_ah + off) = hi;
                    *(uint32_t*)(g_al + off) = lo;
                }
            }
        }
}

// ===========================================================================
extern "C" void kernel_launch(void* const* d_in, const int* in_sizes, int n_in,
                              void* d_out, int out_size)
{
    const float* x          = (const float*)d_in[0];
    const float* mask       = (const float*)d_in[1];
    const float* qkv_w      = (const float*)d_in[2];
    const float* proj_w     = (const float*)d_in[3];
    const float* proj_b     = (const float*)d_in[4];
    const float* bias_table = (const float*)d_in[5];

    int B  = in_sizes[0] / (NTOK * CDIM);
    int nW = in_sizes[1] / (NTOK * NTOK);
    if (B > MAXB) B = MAXB;
    if (nW > MAXNW) nW = MAXNW;
    const int M = B * NTOK;
    const float scale = 0.17677669529663689f;   // 32^-0.5

    const size_t smem_g = (size_t)STAGE_ELEMS * 2 * sizeof(__nv_bfloat16); // 75776
    const size_t smem_a = 56320 + 39200;                                   // 95520

    cudaFuncSetAttribute(gemm2,  cudaFuncAttributeMaxDynamicSharedMemorySize, (int)smem_g);
    cudaFuncSetAttribute(gemm2b, cudaFuncAttributeMaxDynamicSharedMemorySize, (int)smem_g);
    cudaFuncSetAttribute(attn4,  cudaFuncAttributeMaxDynamicSharedMemorySize, (int)smem_a);

    void* xh_p   = nullptr; cudaGetSymbolAddress(&xh_p,   g_xh);
    void* xl_p   = nullptr; cudaGetSymbolAddress(&xl_p,   g_xl);
    void* qkvh_p = nullptr; cudaGetSymbolAddress(&qkvh_p, g_qkvh);
    void* qkvl_p = nullptr; cudaGetSymbolAddress(&qkvl_p, g_qkvl);
    void* ah_p   = nullptr; cudaGetSymbolAddress(&ah_p,   g_ah);
    void* al_p   = nullptr; cudaGetSymbolAddress(&al_p,   g_al);
    void* wqh_p  = nullptr; cudaGetSymbolAddress(&wqh_p,  g_wqh);
    void* wql_p  = nullptr; cudaGetSymbolAddress(&wql_p,  g_wql);
    void* wph_p  = nullptr; cudaGetSymbolAddress(&wph_p,  g_wph);
    void* wpl_p  = nullptr; cudaGetSymbolAddress(&wpl_p,  g_wpl);

    // input/weight splits (q-scale folded into Wq columns 0..255)
    {
        int n4 = M * CDIM / 4;
        convert_split<<<(n4 + 255) / 256, 256>>>(x, (__nv_bfloat16*)xh_p,
                                                 (__nv_bfloat16*)xl_p, n4, 64, 0, 1.f);
        int w1 = CDIM * 3 * CDIM / 4;
        convert_split<<<(w1 + 255) / 256, 256>>>(qkv_w, (__nv_bfloat16*)wqh_p,
                                                 (__nv_bfloat16*)wql_p, w1, 192, 64, scale);
        int w2 = CDIM * CDIM / 4;
        convert_split<<<(w2 + 255) / 256, 256>>>(proj_w, (__nv_bfloat16*)wph_p,
                                                 (__nv_bfloat16*)wpl_p, w2, 64, 0, 1.f);
        int nbm = nW * NHEAD * NTOK * 100;
        prep_bm<<<(nbm + 255) / 256, 256>>>(mask, bias_table, nW);
    }

    dim3 g1((M + BM - 1) / BM, (3 * CDIM) / BN);
    gemm2b<<<g1, 256, smem_g>>>((__nv_bfloat16*)xh_p, (__nv_bfloat16*)xl_p,
                                (__nv_bfloat16*)wqh_p, (__nv_bfloat16*)wql_p,
                                (__nv_bfloat16*)qkvh_p, (__nv_bfloat16*)qkvl_p,
                                M, 3 * CDIM);

    attn4<<<B * NHEAD, 128, smem_a>>>((__nv_bfloat16*)qkvh_p,
                                      (__nv_bfloat16*)qkvl_p, nW);

    dim3 g2d((M + BM - 1) / BM, CDIM / BN);
    gemm2<<<g2d, 256, smem_g>>>((__nv_bfloat16*)ah_p, (__nv_bfloat16*)al_p,
                                (__nv_bfloat16*)wph_p, (__nv_bfloat16*)wpl_p,
                                proj_b, (float*)d_out, M, CDIM);
}

// round 13
// speedup vs baseline: 3.9712x; 1.0325x over previous
#include <cuda_runtime.h>
#include <cuda_bf16.h>
#include <math.h>
#include <stdint.h>

#define NTOK 98
#define CDIM 256
#define NHEAD 8
#define DH 32
#define MAXB 2048
#define MAXM (MAXB * NTOK)
#define MAXNW 64

// scratch (no allocs allowed -> device globals)
__device__ __nv_bfloat16 g_xh[(size_t)MAXM * CDIM];
__device__ __nv_bfloat16 g_xl[(size_t)MAXM * CDIM];
__device__ __nv_bfloat16 g_qkvh[(size_t)MAXM * 3 * CDIM];   // qkv hi [B*N,768]
__device__ __nv_bfloat16 g_qkvl[(size_t)MAXM * 3 * CDIM];   // qkv lo
__device__ __nv_bfloat16 g_ah[(size_t)MAXM * CDIM];         // attn out hi
__device__ __nv_bfloat16 g_al[(size_t)MAXM * CDIM];         // attn out lo
__device__ __nv_bfloat16 g_wqh[CDIM * 3 * CDIM];
__device__ __nv_bfloat16 g_wql[CDIM * 3 * CDIM];
__device__ __nv_bfloat16 g_wph[CDIM * CDIM];
__device__ __nv_bfloat16 g_wpl[CDIM * CDIM];
__device__ float g_bm[(size_t)MAXNW * NHEAD * NTOK * 100];  // bias+mask slabs

extern __shared__ unsigned char smem_raw[];

// ===========================================================================
// helpers
// ===========================================================================
__device__ __forceinline__ uint32_t smem_u32(const void* p) {
    return (uint32_t)__cvta_generic_to_shared(p);
}
__device__ __forceinline__ void ldsm_x4(uint32_t* r, uint32_t a) {
    asm volatile("ldmatrix.sync.aligned.m8n8.x4.shared.b16 {%0,%1,%2,%3},[%4];"
                 : "=r"(r[0]), "=r"(r[1]), "=r"(r[2]), "=r"(r[3]) : "r"(a));
}
__device__ __forceinline__ void ldsm_x4t(uint32_t* r, uint32_t a) {
    asm volatile("ldmatrix.sync.aligned.m8n8.x4.trans.shared.b16 {%0,%1,%2,%3},[%4];"
                 : "=r"(r[0]), "=r"(r[1]), "=r"(r[2]), "=r"(r[3]) : "r"(a));
}
__device__ __forceinline__ void mma16816(float* c, const uint32_t* a,
                                         uint32_t b0, uint32_t b1) {
    asm volatile("mma.sync.aligned.m16n8k16.row.col.f32.bf16.bf16.f32 "
                 "{%0,%1,%2,%3},{%4,%5,%6,%7},{%8,%9},{%0,%1,%2,%3};"
                 : "+f"(c[0]), "+f"(c[1]), "+f"(c[2]), "+f"(c[3])
                 : "r"(a[0]), "r"(a[1]), "r"(a[2]), "r"(a[3]), "r"(b0), "r"(b1));
}
#define CP16(dst, src) \
    asm volatile("cp.async.cg.shared.global [%0],[%1],16;" :: "r"(dst), "l"(src))
#define CP_COMMIT() asm volatile("cp.async.commit_group;")
#define CP_WAIT0()  asm volatile("cp.async.wait_group 0;")
#define CP_WAIT1()  asm volatile("cp.async.wait_group 1;")

// fast exp on fma/alu pipes
__device__ __forceinline__ float fast_exp(float x) {
    x = fmaxf(x, -80.f);
    float t = x * 1.4426950408889634f;
    float r = t + 12582912.f;
    int   k = __float_as_int(r) - 0x4B400000;
    float f = t - (r - 12582912.f);
    float u = f * 0.6931471805599453f;
    float p = 8.3333333e-3f;
    p = fmaf(p, u, 4.1666667e-2f);
    p = fmaf(p, u, 1.6666667e-1f);
    p = fmaf(p, u, 5.0e-1f);
    p = fmaf(p, u, 1.0f);
    p = fmaf(p, u, 1.0f);
    return p * __int_as_float((k + 127) << 23);
}

// split x,y -> packed bf16 hi pair (return) + lo pair (*lo); low 16 bits = x
__device__ __forceinline__ uint32_t pack_hi_lo(float x, float y, uint32_t* lo) {
    __nv_bfloat16 hx = __float2bfloat16(x), hy = __float2bfloat16(y);
    __nv_bfloat16 lx = __float2bfloat16(x - __bfloat162float(hx));
    __nv_bfloat16 ly = __float2bfloat16(y - __bfloat162float(hy));
    *lo = ((uint32_t)__bfloat16_as_ushort(ly) << 16) | __bfloat16_as_ushort(lx);
    return ((uint32_t)__bfloat16_as_ushort(hy) << 16) | __bfloat16_as_ushort(hx);
}

__device__ __forceinline__ int rel_base(int t) {
    int d = t / 49, rem = t % 49;
    return d * 169 + (rem / 7) * 13 + (rem % 7);
}

// ===========================================================================
// fp32 -> bf16 hi/lo split; cols < nscale4 float4-groups of each row get *scale
// ===========================================================================
__global__ void convert_split(const float* __restrict__ s,
                              __nv_bfloat16* __restrict__ hi,
                              __nv_bfloat16* __restrict__ lo,
                              int n4, int width4, int nscale4, float scale)
{
    int i = blockIdx.x * blockDim.x + threadIdx.x;
    if (i >= n4) return;
    float4 v = ((const float4*)s)[i];
    float sc = ((i % width4) < nscale4) ? scale : 1.f;
    v.x *= sc; v.y *= sc; v.z *= sc; v.w *= sc;
    __nv_bfloat16 h0 = __float2bfloat16(v.x), h1 = __float2bfloat16(v.y);
    __nv_bfloat16 h2 = __float2bfloat16(v.z), h3 = __float2bfloat16(v.w);
    __nv_bfloat16 l0 = __float2bfloat16(v.x - __bfloat162float(h0));
    __nv_bfloat16 l1 = __float2bfloat16(v.y - __bfloat162float(h1));
    __nv_bfloat16 l2 = __float2bfloat16(v.z - __bfloat162float(h2));
    __nv_bfloat16 l3 = __float2bfloat16(v.w - __bfloat162float(h3));
    ((__nv_bfloat162*)hi)[2 * i]     = __nv_bfloat162(h0, h1);
    ((__nv_bfloat162*)hi)[2 * i + 1] = __nv_bfloat162(h2, h3);
    ((__nv_bfloat162*)lo)[2 * i]     = __nv_bfloat162(l0, l1);
    ((__nv_bfloat162*)lo)[2 * i + 1] = __nv_bfloat162(l2, l3);
}

// ===========================================================================
// bm[wi][h][n][m(pad 100)] = bias_table[relidx(n,m)][h] + mask[wi][n][m]
// ===========================================================================
__global__ void prep_bm(const float* __restrict__ mask,
                        const float* __restrict__ bias_table, int nW)
{
    int idx = blockIdx.x * blockDim.x + threadIdx.x;
    int total = nW * NHEAD * NTOK * 100;
    if (idx >= total) return;
    int m  = idx % 100;
    int n  = (idx / 100) % NTOK;
    int h  = (idx / (100 * NTOK)) % NHEAD;
    int wi = idx / (100 * NTOK * NHEAD);
    float v = 0.f;
    if (m < NTOK) {
        int ri = rel_base(n) - rel_base(m) + 253;
        v = __ldg(&bias_table[ri * NHEAD + h])
          + __ldg(&mask[((size_t)wi * NTOK + n) * NTOK + m]);
    }
    g_bm[idx] = v;
}

// ===========================================================================
// GEMM core: bf16x3, cp.async 3-stage, one barrier/iter.  BM=128 BN=128 BK=32.
// ===========================================================================
#define BM 128
#define BN 128
#define BK 32
#define SA 40
#define SB 136
#define A_ELEMS (BM * SA)
#define B_ELEMS (BK * SB)
#define STAGE_ELEMS (2 * A_ELEMS + 2 * B_ELEMS)
#define NSTAGE 3

static __device__ __forceinline__ void g2_load(
    const __nv_bfloat16* __restrict__ Ah, const __nv_bfloat16* __restrict__ Al,
    const __nv_bfloat16* __restrict__ Bh, const __nv_bfloat16* __restrict__ Bl,
    __nv_bfloat16* sm, int s, int M, int N, int m0, int n0, int kt, int tid)
{
    __nv_bfloat16* sAh = sm + (size_t)s * STAGE_ELEMS;
    __nv_bfloat16* sBh = sAh + 2 * A_ELEMS;
    #pragma unroll
    for (int i = 0; i < 2; ++i) {
        int idx = tid + i * 256;
        int row = idx >> 2, ch = (idx & 3) << 3;
        int gr = m0 + row; if (gr >= M) gr = M - 1;
        size_t go = (size_t)gr * 256 + kt * BK + ch;
        uint32_t so = smem_u32(sAh + row * SA + ch);
        CP16(so, Ah + go);
        CP16(so + (uint32_t)(A_ELEMS * 2), Al + go);
    }
    #pragma unroll
    for (int i = 0; i < 2; ++i) {
        int idx = tid + i * 256;
        int row = idx >> 4, ch = (idx & 15) << 3;
        size_t go = (size_t)(kt * BK + row) * N + n0 + ch;
        uint32_t so = smem_u32(sBh + row * SB + ch);
        CP16(so, Bh + go);
        CP16(so + (uint32_t)(B_ELEMS * 2), Bl + go);
    }
}

static __device__ __forceinline__ void g2_compute(const __nv_bfloat16* sm, int s,
                                                  int wr, int wc, int lane,
                                                  float acc[2][8][4])
{
    const __nv_bfloat16* sAh = sm + (size_t)s * STAGE_ELEMS;
    const __nv_bfloat16* sAl = sAh + A_ELEMS;
    const __nv_bfloat16* sBh = sAl + A_ELEMS;
    const __nv_bfloat16* sBl = sBh + B_ELEMS;
    const int sub = lane >> 3, w8 = lane & 7;
    #pragma unroll
    for (int ks = 0; ks < BK; ks += 16) {
        uint32_t ah[2][4], al[2][4], bh[4][4], bl[4][4];
        #pragma unroll
        for (int mf = 0; mf < 2; ++mf) {
            int row = wr + mf * 16 + w8 + (sub & 1) * 8;
            int col = ks + (sub >> 1) * 8;
            ldsm_x4(ah[mf], smem_u32(sAh + row * SA + col));
            ldsm_x4(al[mf], smem_u32(sAl + row * SA + col));
        }
        #pragma unroll
        for (int nf = 0; nf < 4; ++nf) {
            int krow = ks + w8 + (sub & 1) * 8;
            int col  = wc + nf * 16 + (sub >> 1) * 8;
            ldsm_x4t(bh[nf], smem_u32(sBh + krow * SB + col));
            ldsm_x4t(bl[nf], smem_u32(sBl + krow * SB + col));
        }
        #pragma unroll
        for (int mf = 0; mf < 2; ++mf)
            #pragma unroll
            for (int nf = 0; nf < 8; ++nf) {
                uint32_t b0h = bh[nf >> 1][(nf & 1) * 2];
                uint32_t b1h = bh[nf >> 1][(nf & 1) * 2 + 1];
                uint32_t b0l = bl[nf >> 1][(nf & 1) * 2];
                uint32_t b1l = bl[nf >> 1][(nf & 1) * 2 + 1];
                mma16816(acc[mf][nf], ah[mf], b0h, b1h);
                mma16816(acc[mf][nf], ah[mf], b0l, b1l);
                mma16816(acc[mf][nf], al[mf], b0h, b1h);
            }
    }
}

// 3-stage mainloop, single barrier per iteration.
// Safety: load target slot (kt+2)%3 == (kt-1)%3, whose compute finished in all
// warps before this iteration's __syncthreads.
#define G2_MAINLOOP()                                                        \
    float acc[2][8][4];                                                      \
    _Pragma("unroll")                                                        \
    for (int i = 0; i < 2; ++i)                                              \
        _Pragma("unroll")                                                    \
        for (int j = 0; j < 8; ++j)                                          \
            _Pragma("unroll")                                                \
            for (int k = 0; k < 4; ++k) acc[i][j][k] = 0.f;                  \
    const int NT = 256 / BK;                                                 \
    g2_load(Ah, Al, Bh, Bl, sm, 0, M, N, m0, n0, 0, tid);                    \
    CP_COMMIT();                                                             \
    g2_load(Ah, Al, Bh, Bl, sm, 1, M, N, m0, n0, 1, tid);                    \
    CP_COMMIT();                                                             \
    _Pragma("unroll 1")                                                      \
    for (int kt = 0; kt < NT; ++kt) {                                        \
        if (kt + 1 < NT) { CP_WAIT1(); } else { CP_WAIT0(); }                \
        __syncthreads();                                                     \
        g2_compute(sm, kt % NSTAGE, wr, wc, lane, acc);                      \
        if (kt + 2 < NT) {                                                   \
            g2_load(Ah, Al, Bh, Bl, sm, (kt + 2) % NSTAGE, M, N, m0, n0,     \
                    kt + 2, tid);                                            \
            CP_COMMIT();                                                     \
        }                                                                    \
    }

// fp32 output + bias (proj path)
__global__ void __launch_bounds__(256, 2)
gemm2(const __nv_bfloat16* __restrict__ Ah, const __nv_bfloat16* __restrict__ Al,
      const __nv_bfloat16* __restrict__ Bh, const __nv_bfloat16* __restrict__ Bl,
      const float* __restrict__ bias, float* __restrict__ C, int M, int N)
{
    __nv_bfloat16* sm = (__nv_bfloat16*)smem_raw;
    const int tid  = threadIdx.x;
    const int warp = tid >> 5, lane = tid & 31;
    const int m0 = blockIdx.x * BM;
    const int n0 = blockIdx.y * BN;
    const int wr = (warp & 3) * 32;
    const int wc = (warp >> 2) * 64;

    G2_MAINLOOP();

    const int r4 = lane >> 2, c2 = (lane & 3) * 2;
    #pragma unroll
    for (int mf = 0; mf < 2; ++mf)
        #pragma unroll
        for (int nf = 0; nf < 8; ++nf) {
            int col = n0 + wc + nf * 8 + c2;
            float b0 = __ldg(bias + col);
            float b1 = __ldg(bias + col + 1);
            int row = m0 + wr + mf * 16 + r4;
            if (row < M) {
                float2 v = make_float2(acc[mf][nf][0] + b0, acc[mf][nf][1] + b1);
                *(float2*)(C + (size_t)row * N + col) = v;
            }
            if (row + 8 < M) {
                float2 v = make_float2(acc[mf][nf][2] + b0, acc[mf][nf][3] + b1);
                *(float2*)(C + (size_t)(row + 8) * N + col) = v;
            }
        }
}

// bf16 hi/lo split output, no bias (qkv path)
__global__ void __launch_bounds__(256, 2)
gemm2b(const __nv_bfloat16* __restrict__ Ah, const __nv_bfloat16* __restrict__ Al,
       const __nv_bfloat16* __restrict__ Bh, const __nv_bfloat16* __restrict__ Bl,
       __nv_bfloat16* __restrict__ Ch, __nv_bfloat16* __restrict__ Cl,
       int M, int N)
{
    __nv_bfloat16* sm = (__nv_bfloat16*)smem_raw;
    const int tid  = threadIdx.x;
    const int warp = tid >> 5, lane = tid & 31;
    const int m0 = blockIdx.x * BM;
    const int n0 = blockIdx.y * BN;
    const int wr = (warp & 3) * 32;
    const int wc = (warp >> 2) * 64;

    G2_MAINLOOP();

    const int r4 = lane >> 2, c2 = (lane & 3) * 2;
    #pragma unroll
    for (int mf = 0; mf < 2; ++mf)
        #pragma unroll
        for (int nf = 0; nf < 8; ++nf) {
            int col = n0 + wc + nf * 8 + c2;
            int row = m0 + wr + mf * 16 + r4;
            if (row < M) {
                uint32_t lo, hi = pack_hi_lo(acc[mf][nf][0], acc[mf][nf][1], &lo);
                *(uint32_t*)(Ch + (size_t)row * N + col) = hi;
                *(uint32_t*)(Cl + (size_t)row * N + col) = lo;
            }
            if (row + 8 < M) {
                uint32_t lo, hi = pack_hi_lo(acc[mf][nf][2], acc[mf][nf][3], &lo);
                *(uint32_t*)(Ch + (size_t)(row + 8) * N + col) = hi;
                *(uint32_t*)(Cl + (size_t)(row + 8) * N + col) = lo;
            }
        }
}

// ===========================================================================
// attn4: one CTA (128 thr) per (window, head). cp.async q/k/v prologue,
// mma core, bm read straight from L2 (slabs are L2-resident, row-contiguous).
// smem: q[128x40]h/l k[112x40]h/l v[112x40]h/l  bf16 = 56320 B
// ===========================================================================
__global__ void __launch_bounds__(128, 2)
attn4(const __nv_bfloat16* __restrict__ Qh, const __nv_bfloat16* __restrict__ Ql,
      int nW)
{
    __nv_bfloat16* qh = (__nv_bfloat16*)smem_raw;   // 128x40
    __nv_bfloat16* ql = qh + 5120;
    __nv_bfloat16* kh = ql + 5120;                  // 112x40
    __nv_bfloat16* kl = kh + 4480;
    __nv_bfloat16* vh = kl + 4480;
    __nv_bfloat16* vl = vh + 4480;

    const int b    = blockIdx.x >> 3;
    const int h    = blockIdx.x & 7;
    const int tid  = threadIdx.x;
    const int lane = tid & 31;
    const int warp = tid >> 5;
    const int wi   = b % nW;

    // zero V padding rows 98..111 (hi+lo)
    {
        uint32_t* zv = (uint32_t*)(vh + 98 * 40);
        uint32_t* zl = (uint32_t*)(vl + 98 * 40);
        for (int i = tid; i < 280; i += 128) { zv[i] = 0; zl[i] = 0; }
    }

    // cp.async: q/k/v hi+lo slabs (32 cols of head h)
    {
        __nv_bfloat16* mats[6] = {qh, ql, kh, kl, vh, vl};
        for (int idx = tid; idx < 2352; idx += 128) {
            int chunk = idx & 3;
            int row   = (idx >> 2) % 98;
            int mat   = idx / 392;
            int grp   = mat >> 1;
            const __nv_bfloat16* src = (mat & 1) ? Ql : Qh;
            size_t go = ((size_t)b * NTOK + row) * 768 + grp * 256 + h * 32 + chunk * 8;
            CP16(smem_u32(mats[mat] + row * 40 + chunk * 8), src + go);
        }
    }
    CP_COMMIT();
    CP_WAIT0();
    __syncthreads();

    const int wr  = warp * 32;
    const int sub = lane >> 3, w8 = lane & 7;
    const int r4  = lane >> 2, c2 = (lane & 3) * 2;

    // ---- S = q k^T (scale pre-folded into Wq), bf16x3 ----------------------
    float S[2][14][4];
    #pragma unroll
    for (int mt = 0; mt < 2; ++mt)
        #pragma unroll
        for (int nt = 0; nt < 14; ++nt)
            #pragma unroll
            for (int i = 0; i < 4; ++i) S[mt][nt][i] = 0.f;

    #pragma unroll
    for (int ks = 0; ks < 2; ++ks) {
        uint32_t aqh[2][4], aql[2][4];
        #pragma unroll
        for (int mt = 0; mt < 2; ++mt) {
            int row = wr + mt * 16 + w8 + (sub & 1) * 8;
            int col = ks * 16 + (sub >> 1) * 8;
            ldsm_x4(aqh[mt], smem_u32(qh + row * 40 + col));
            ldsm_x4(aql[mt], smem_u32(ql + row * 40 + col));
        }
        #pragma unroll
        for (int nt2 = 0; nt2 < 7; ++nt2) {
            uint32_t bkh[4], bkl[4];
            int row = nt2 * 16 + w8 + (sub & 1) * 8;
            int col = ks * 16 + (sub >> 1) * 8;
            ldsm_x4(bkh, smem_u32(kh + row * 40 + col));
            ldsm_x4(bkl, smem_u32(kl + row * 40 + col));
            #pragma unroll
            for (int mt = 0; mt < 2; ++mt) {
                mma16816(S[mt][nt2 * 2],     aqh[mt], bkh[0], bkh[2]);
                mma16816(S[mt][nt2 * 2],     aqh[mt], bkl[0], bkl[2]);
                mma16816(S[mt][nt2 * 2],     aql[mt], bkh[0], bkh[2]);
                mma16816(S[mt][nt2 * 2 + 1], aqh[mt], bkh[1], bkh[3]);
                mma16816(S[mt][nt2 * 2 + 1], aqh[mt], bkl[1], bkl[3]);
                mma16816(S[mt][nt2 * 2 + 1], aql[mt], bkh[1], bkh[3]);
            }
        }
    }

    // ---- + (bias+mask) direct from L2, -1e9 padding ------------------------
    const float* slab = g_bm + (size_t)(wi * NHEAD + h) * (NTOK * 100);
    #pragma unroll
    for (int mt = 0; mt < 2; ++mt) {
        #pragma unroll
        for (int half = 0; half < 2; ++half) {
            int row = wr + mt * 16 + r4 + half * 8;
            bool rv = row < NTOK;
            const float* bmrow = slab + (rv ? row : 0) * 100;
            #pragma unroll
            for (int nt = 0; nt < 14; ++nt) {
                int col = nt * 8 + c2;
                float* sp = &S[mt][nt][half * 2];
                if (rv && col < NTOK) {
                    float2 bm2 = __ldg((const float2*)(bmrow + col));
                    sp[0] += bm2.x;
                    sp[1] += bm2.y;
                } else {
                    sp[0] = -1e9f;
                    sp[1] = -1e9f;
                }
            }
        }
    }

    // ---- softmax in registers (deferred normalization) ---------------------
    float inv_[2][2];
    #pragma unroll
    for (int mt = 0; mt < 2; ++mt)
        #pragma unroll
        for (int half = 0; half < 2; ++half) {
            float mx = -1e30f;
            #pragma unroll
            for (int nt = 0; nt < 14; ++nt)
                mx = fmaxf(mx, fmaxf(S[mt][nt][half * 2], S[mt][nt][half * 2 + 1]));
            mx = fmaxf(mx, __shfl_xor_sync(0xffffffffu, mx, 1));
            mx = fmaxf(mx, __shfl_xor_sync(0xffffffffu, mx, 2));
            float sum = 0.f;
            #pragma unroll
            for (int nt = 0; nt < 14; ++nt) {
                float e0 = fast_exp(S[mt][nt][half * 2]     - mx);
                float e1 = fast_exp(S[mt][nt][half * 2 + 1] - mx);
                S[mt][nt][half * 2]     = e0;
                S[mt][nt][half * 2 + 1] = e1;
                sum += e0 + e1;
            }
            sum += __shfl_xor_sync(0xffffffffu, sum, 1);
            sum += __shfl_xor_sync(0xffffffffu, sum, 2);
            inv_[mt][half] = __fdividef(1.f, sum);
        }

    // ---- O = P @ V (bf16x3) ------------------------------------------------
    float O[2][4][4];
    #pragma unroll
    for (int mt = 0; mt < 2; ++mt)
        #pragma unroll
        for (int nf = 0; nf < 4; ++nf)
            #pragma unroll
            for (int i = 0; i < 4; ++i) O[mt][nf][i] = 0.f;

    #pragma unroll
    for (int kt = 0; kt < 7; ++kt) {
        uint32_t vfh[2][4], vfl[2][4];
        #pragma unroll
        for (int j = 0; j < 2; ++j) {
            int row = kt * 16 + w8 + (sub & 1) * 8;
            int col = j * 16 + (sub >> 1) * 8;
            ldsm_x4t(vfh[j], smem_u32(vh + row * 40 + col));
            ldsm_x4t(vfl[j], smem_u32(vl + row * 40 + col));
        }
        #pragma unroll
        for (int mt = 0; mt < 2; ++mt) {
            const float* cA = S[mt][2 * kt];
            const float* cB = S[mt][2 * kt + 1];
            uint32_t Ph[4], Pl[4];
            Ph[0] = pack_hi_lo(cA[0], cA[1], &Pl[0]);
            Ph[1] = pack_hi_lo(cA[2], cA[3], &Pl[1]);
            Ph[2] = pack_hi_lo(cB[0], cB[1], &Pl[2]);
            Ph[3] = pack_hi_lo(cB[2], cB[3], &Pl[3]);
            #pragma unroll
            for (int nf = 0; nf < 4; ++nf) {
                uint32_t b0h = vfh[nf >> 1][(nf & 1) * 2];
                uint32_t b1h = vfh[nf >> 1][(nf & 1) * 2 + 1];
                uint32_t b0l = vfl[nf >> 1][(nf & 1) * 2];
                uint32_t b1l = vfl[nf >> 1][(nf & 1) * 2 + 1];
                mma16816(O[mt][nf], Ph, b0h, b1h);
                mma16816(O[mt][nf], Ph, b0l, b1l);
                mma16816(O[mt][nf], Pl, b0h, b1h);
            }
        }
    }

    // ---- store normalized, hi/lo split, vectorized -------------------------
    #pragma unroll
    for (int mt = 0; mt < 2; ++mt)
        #pragma unroll
        for (int half = 0; half < 2; ++half) {
            int row = wr + mt * 16 + r4 + half * 8;
            if (row < NTOK) {
                float s = inv_[mt][half];
                #pragma unroll
                for (int nf = 0; nf < 4; ++nf) {
                    float v0 = O[mt][nf][half * 2]     * s;
                    float v1 = O[mt][nf][half * 2 + 1] * s;
                    int col = h * 32 + nf * 8 + c2;
                    size_t off = ((size_t)b * NTOK + row) * CDIM + col;
                    uint32_t lo, hi = pack_hi_lo(v0, v1, &lo);
                    *(uint32_t*)(g_ah + off) = hi;
                    *(uint32_t*)(g_al + off) = lo;
                }
            }
        }
}

// ===========================================================================
extern "C" void kernel_launch(void* const* d_in, const int* in_sizes, int n_in,
                              void* d_out, int out_size)
{
    const float* x          = (const float*)d_in[0];
    const float* mask       = (const float*)d_in[1];
    const float* qkv_w      = (const float*)d_in[2];
    const float* proj_w     = (const float*)d_in[3];
    const float* proj_b     = (const float*)d_in[4];
    const float* bias_table = (const float*)d_in[5];

    int B  = in_sizes[0] / (NTOK * CDIM);
    int nW = in_sizes[1] / (NTOK * NTOK);
    if (B > MAXB) B = MAXB;
    if (nW > MAXNW) nW = MAXNW;
    const int M = B * NTOK;
    const float scale = 0.17677669529663689f;   // 32^-0.5

    const size_t smem_g = (size_t)STAGE_ELEMS * NSTAGE * sizeof(__nv_bfloat16); // 113664
    const size_t smem_a = 56320;

    cudaFuncSetAttribute(gemm2,  cudaFuncAttributeMaxDynamicSharedMemorySize, (int)smem_g);
    cudaFuncSetAttribute(gemm2b, cudaFuncAttributeMaxDynamicSharedMemorySize, (int)smem_g);
    cudaFuncSetAttribute(attn4,  cudaFuncAttributeMaxDynamicSharedMemorySize, (int)smem_a);

    void* xh_p   = nullptr; cudaGetSymbolAddress(&xh_p,   g_xh);
    void* xl_p   = nullptr; cudaGetSymbolAddress(&xl_p,   g_xl);
    void* qkvh_p = nullptr; cudaGetSymbolAddress(&qkvh_p, g_qkvh);
    void* qkvl_p = nullptr; cudaGetSymbolAddress(&qkvl_p, g_qkvl);
    void* ah_p   = nullptr; cudaGetSymbolAddress(&ah_p,   g_ah);
    void* al_p   = nullptr; cudaGetSymbolAddress(&al_p,   g_al);
    void* wqh_p  = nullptr; cudaGetSymbolAddress(&wqh_p,  g_wqh);
    void* wql_p  = nullptr; cudaGetSymbolAddress(&wql_p,  g_wql);
    void* wph_p  = nullptr; cudaGetSymbolAddress(&wph_p,  g_wph);
    void* wpl_p  = nullptr; cudaGetSymbolAddress(&wpl_p,  g_wpl);

    // input/weight splits (q-scale folded into Wq columns 0..255)
    {
        int n4 = M * CDIM / 4;
        convert_split<<<(n4 + 255) / 256, 256>>>(x, (__nv_bfloat16*)xh_p,
                                                 (__nv_bfloat16*)xl_p, n4, 64, 0, 1.f);
        int w1 = CDIM * 3 * CDIM / 4;
        convert_split<<<(w1 + 255) / 256, 256>>>(qkv_w, (__nv_bfloat16*)wqh_p,
                                                 (__nv_bfloat16*)wql_p, w1, 192, 64, scale);
        int w2 = CDIM * CDIM / 4;
        convert_split<<<(w2 + 255) / 256, 256>>>(proj_w, (__nv_bfloat16*)wph_p,
                                                 (__nv_bfloat16*)wpl_p, w2, 64, 0, 1.f);
        int nbm = nW * NHEAD * NTOK * 100;
        prep_bm<<<(nbm + 255) / 256, 256>>>(mask, bias_table, nW);
    }

    dim3 g1((M + BM - 1) / BM, (3 * CDIM) / BN);
    gemm2b<<<g1, 256, smem_g>>>((__nv_bfloat16*)xh_p, (__nv_bfloat16*)xl_p,
                                (__nv_bfloat16*)wqh_p, (__nv_bfloat16*)wql_p,
                                (__nv_bfloat16*)qkvh_p, (__nv_bfloat16*)qkvl_p,
                                M, 3 * CDIM);

    attn4<<<B * NHEAD, 128, smem_a>>>((__nv_bfloat16*)qkvh_p,
                                      (__nv_bfloat16*)qkvl_p, nW);

    dim3 g2d((M + BM - 1) / BM, CDIM / BN);
    gemm2<<<g2d, 256, smem_g>>>((__nv_bfloat16*)ah_p, (__nv_bfloat16*)al_p,
                                (__nv_bfloat16*)wph_p, (__nv_bfloat16*)wpl_p,
                                proj_b, (float*)d_out, M, CDIM);
}